// round 10
// baseline (speedup 1.0000x reference)
#include <cuda_runtime.h>
#include <cstdint>

#define NROWS 594880   // 55 * 64 * 169
#define NN    10816    // 64 * 169 rows per timestep
#define TSTEPS 55
#define HL    100
#define NIMG  3520     // 55 * 64 images of 13x13

typedef unsigned long long ull;

// ---------------- f32x2 packed-math helpers (sm_103a FFMA2) -----------------
__device__ __forceinline__ ull pk2(float lo, float hi) {
    ull r; asm("mov.b64 %0,{%1,%2};" : "=l"(r) : "f"(lo), "f"(hi)); return r;
}
__device__ __forceinline__ void upk2(ull v, float& lo, float& hi) {
    asm("mov.b64 {%0,%1},%2;" : "=f"(lo), "=f"(hi) : "l"(v));
}
// "+l" ties the accumulator's input and output register pair — without it,
// ptxas may materialize a fresh pair per FMA and insert 2 MOVs to copy.
__device__ __forceinline__ void fma2(ull& d, ull a, ull b) {
    asm("fma.rn.f32x2 %0,%1,%2,%0;" : "+l"(d) : "l"(a), "l"(b));
}

__device__ __forceinline__ float sigm(float x) {
    return __fdividef(1.f, 1.f + __expf(-x));
}
__device__ __forceinline__ float tanha(float x) {
    return __fdividef(2.f, 1.f + __expf(-2.f * x)) - 1.f;
}

// ---------------- static device scratch -------------------------------------
__device__ float g_act0[(size_t)NROWS * 30];
__device__ float g_act1[(size_t)NROWS * 30];
__device__ float g_xw [(size_t)NROWS * 400];
__device__ float g_hs1[(size_t)NROWS * HL];
__device__ float g_hs2[(size_t)NROWS * HL];

// ---------------- input transpose: [B,13,13,L,C] -> [(l*64+b)*169+pix, 24] --
__global__ void transpose_in(const float* __restrict__ x, float* __restrict__ y) {
    long idx = (long)blockIdx.x * blockDim.x + threadIdx.x;
    const long total = (long)NROWS * 6;
    if (idx >= total) return;
    int  c4  = (int)(idx % 6);
    long row = idx / 6;
    int  pix = (int)(row % 169);
    long t1  = row / 169;
    int  b   = (int)(t1 % 64);
    int  l   = (int)(t1 / 64);
    long src = (((long)(b * 169 + pix)) * 55 + l) * 24 + c4 * 4;
    reinterpret_cast<float4*>(y)[row * 6 + c4] =
        *reinterpret_cast<const float4*>(x + src);
}

// ---------------- fused 1x1 conv chain: 4 layers, activations in registers --
#define C1_STG 33
__global__ __launch_bounds__(128, 3)
void conv1_fused(const float* __restrict__ A,
                 const float* __restrict__ w0, const float* __restrict__ b0,
                 const float* __restrict__ w1, const float* __restrict__ b1,
                 const float* __restrict__ w2, const float* __restrict__ b2,
                 const float* __restrict__ w3, const float* __restrict__ b3,
                 float* __restrict__ Cout, long M) {
    extern __shared__ float sm[];
    float* stage = sm;                 // [256][33], scalar access only
    float* sw    = sm + 256 * C1_STG;  // 720 + 3*900 = 3420 (base even: 8448)
    float* sb    = sw + 3420;          // 4 x 30

    const int tid  = threadIdx.x;
    const long row0 = (long)blockIdx.x * 256;

    for (int i = tid; i < 720; i += 128) sw[i] = w0[i];
    for (int i = tid; i < 900; i += 128) {
        sw[720 + i]  = w1[i];
        sw[1620 + i] = w2[i];
        sw[2520 + i] = w3[i];
    }
    if (tid < 30) {
        sb[tid] = b0[tid]; sb[30 + tid] = b1[tid];
        sb[60 + tid] = b2[tid]; sb[90 + tid] = b3[tid];
    }
    for (int f = tid; f < 1536; f += 128) {
        int r = f / 6, c4 = f - r * 6;
        long gr = row0 + r;
        float4 v = make_float4(0.f, 0.f, 0.f, 0.f);
        if (gr < M) v = *reinterpret_cast<const float4*>(A + gr * 24 + 4 * c4);
        float* d = &stage[r * C1_STG + 4 * c4];
        d[0] = v.x; d[1] = v.y; d[2] = v.z; d[3] = v.w;
    }
    __syncthreads();

    float a0[30], a1[30];
    {
        const float* s0 = &stage[(2 * tid) * C1_STG];
        const float* s1 = &stage[(2 * tid + 1) * C1_STG];
        #pragma unroll
        for (int k = 0; k < 24; k++) { a0[k] = s0[k]; a1[k] = s1[k]; }
    }

    ull acc0[15], acc1[15];
    #pragma unroll 1
    for (int layer = 0; layer < 4; layer++) {
        const int K = (layer == 0) ? 24 : 30;
        const float* wl = sw + ((layer == 0) ? 0 : 720 + (layer - 1) * 900);
        const float* bl = sb + layer * 30;
        #pragma unroll
        for (int p = 0; p < 15; p++) { acc0[p] = 0ull; acc1[p] = 0ull; }
        #pragma unroll 6
        for (int k = 0; k < K; k++) {
            ull ad0 = pk2(a0[k], a0[k]);
            ull ad1 = pk2(a1[k], a1[k]);
            const ull* wk = reinterpret_cast<const ull*>(&wl[k * 30]);
            #pragma unroll
            for (int p = 0; p < 15; p++) {
                ull bv = wk[p];
                fma2(acc0[p], ad0, bv);
                fma2(acc1[p], ad1, bv);
            }
        }
        #pragma unroll
        for (int p = 0; p < 15; p++) {
            float l0, h0, l1, h1;
            upk2(acc0[p], l0, h0);
            upk2(acc1[p], l1, h1);
            float be = bl[2 * p], bo = bl[2 * p + 1];
            a0[2 * p]     = fmaxf(l0 + be, 0.f);
            a0[2 * p + 1] = fmaxf(h0 + bo, 0.f);
            a1[2 * p]     = fmaxf(l1 + be, 0.f);
            a1[2 * p + 1] = fmaxf(h1 + bo, 0.f);
        }
    }

    __syncthreads();
    {
        float* s0 = &stage[(2 * tid) * C1_STG];
        float* s1 = &stage[(2 * tid + 1) * C1_STG];
        #pragma unroll
        for (int k = 0; k < 30; k++) { s0[k] = a0[k]; s1[k] = a1[k]; }
    }
    __syncthreads();
    for (int f = tid; f < 256 * 15; f += 128) {
        int r = f / 15, c2 = f - r * 15;
        long gr = row0 + r;
        if (gr < M) {
            const float* s = &stage[r * C1_STG + 2 * c2];
            *reinterpret_cast<float2*>(&Cout[gr * 30 + 2 * c2]) =
                make_float2(s[0], s[1]);
        }
    }
}

// ---------------- bulk LSTM x-projection GEMM: C = A[M,K]@B[K,400] + bias ---
template<int K>
__global__ __launch_bounds__(320, 2)
void gemm_xw(const float* __restrict__ A, const float* __restrict__ B,
             const float* __restrict__ bias, float* __restrict__ C, long M) {
    constexpr int BM = 128, BN = 100, AS = BM + 3;   // 131
    extern __shared__ float sm[];
    float* Asm = sm;                 // [K][AS]
    float* Bsm = sm + K * AS;        // [K][BN]
    float* stg = sm;                 // alias (post-sync), stride 101, scalar

    const int tid = threadIdx.x;
    const int tc = tid / 32, tr = tid % 32;
    const long row0 = (long)blockIdx.y * BM;
    const int  col0 = blockIdx.x * BN;

    for (int i = tid; i < BM * K; i += 320) {
        int r = i / K, k = i - r * K;
        long gr = row0 + r;
        Asm[k * AS + r] = (gr < M) ? A[gr * (long)K + k] : 0.f;
    }
    for (int i = tid; i < K * BN; i += 320) {
        int k = i / BN, n = i - k * BN;
        Bsm[i] = B[(size_t)k * 400 + col0 + n];
    }
    __syncthreads();

    const int cbase = tc * 10;
    ull acc[4][5];
    #pragma unroll
    for (int j = 0; j < 4; j++)
        #pragma unroll
        for (int p = 0; p < 5; p++) acc[j][p] = 0ull;

    #pragma unroll 10
    for (int k = 0; k < K; k++) {
        ull bv[5];
        #pragma unroll
        for (int p = 0; p < 5; p++)
            bv[p] = *reinterpret_cast<const ull*>(&Bsm[k * BN + cbase + 2 * p]);
        const float* ar = &Asm[k * AS + tr];
        #pragma unroll
        for (int j = 0; j < 4; j++) {
            float a = ar[32 * j];
            ull ad = pk2(a, a);
            #pragma unroll
            for (int p = 0; p < 5; p++) fma2(acc[j][p], ad, bv[p]);
        }
    }

    float bl[5], bh[5];
    #pragma unroll
    for (int p = 0; p < 5; p++) {
        bl[p] = bias[col0 + cbase + 2 * p];
        bh[p] = bias[col0 + cbase + 2 * p + 1];
    }

    #pragma unroll 1
    for (int ch = 0; ch < 2; ch++) {
        __syncthreads();
        #pragma unroll
        for (int jj = 0; jj < 2; jj++) {
            int j = ch * 2 + jj;
            int rl = jj * 32 + tr;
            float* sr = &stg[rl * 101 + cbase];
            #pragma unroll
            for (int p = 0; p < 5; p++) {
                float lo, hi;
                upk2(acc[j][p], lo, hi);
                sr[2 * p]     = lo + bl[p];
                sr[2 * p + 1] = hi + bh[p];
            }
        }
        __syncthreads();
        for (int i = tid; i < 64 * 50; i += 320) {
            int r = i / 50, c2 = i - r * 50;
            long gr = row0 + ch * 64 + r;
            if (gr < M) {
                const float* s = &stg[r * 101 + 2 * c2];
                *reinterpret_cast<float2*>(&C[gr * 400 + col0 + 2 * c2]) =
                    make_float2(s[0], s[1]);
            }
        }
    }
}

// ---------------- 5x5 SAME conv v6: zero-waste asymmetric p-split -----------
#define CONV_SIN 9180   // 30 * 17 * 18
template<int NP>
__device__ __forceinline__ void conv_tile(const float* __restrict__ bi,
                                          const float* __restrict__ sw,
                                          int orow, int co0, int colbase,
                                          ull (&acc)[NP][5]) {
    #pragma unroll 2
    for (int ci = 0; ci < 30; ci++) {
        const float* bci = bi + ci * 306 + colbase;
        #pragma unroll 1
        for (int ki = 0; ki < 5; ki++) {
            const float* vrow = bci + (orow + ki) * 18;   // even offsets
            float2 t[NP + 2];
            #pragma unroll
            for (int q = 0; q < NP + 2; q++)
                t[q] = *reinterpret_cast<const float2*>(&vrow[2 * q]);
            ull va[NP + 2], vs[NP + 1];
            #pragma unroll
            for (int q = 0; q < NP + 2; q++) va[q] = pk2(t[q].x, t[q].y);
            #pragma unroll
            for (int q = 0; q < NP + 1; q++) vs[q] = pk2(t[q].y, t[q + 1].x);
            #pragma unroll
            for (int kj = 0; kj < 5; kj++) {
                const float* wp = sw + ((ki * 5 + kj) * 30 + ci) * 30 + co0;
                ull wd[5];
                #pragma unroll
                for (int c = 0; c < 5; c++) {
                    float wv = wp[c];
                    wd[c] = pk2(wv, wv);
                }
                #pragma unroll
                for (int pp = 0; pp < NP; pp++) {
                    ull a = (kj == 0) ? va[pp] :
                            (kj == 1) ? vs[pp] :
                            (kj == 2) ? va[pp + 1] :
                            (kj == 3) ? vs[pp + 1] : va[pp + 2];
                    #pragma unroll
                    for (int c = 0; c < 5; c++) fma2(acc[pp][c], a, wd[c]);
                }
            }
        }
    }
}

template<int NP>
__device__ __forceinline__ void conv_epilogue(float* __restrict__ so,
                                              const float* __restrict__ bias,
                                              int co0, int pg0, ull (&acc)[NP][5]) {
    float bv[5];
    #pragma unroll
    for (int c = 0; c < 5; c++) bv[c] = bias[co0 + c];
    #pragma unroll
    for (int pp = 0; pp < NP; pp++) {
        const int pg = pg0 + pp;
        #pragma unroll
        for (int c = 0; c < 5; c++) {
            float lo, hi;
            upk2(acc[pp][c], lo, hi);
            so[(2 * pg) * 30 + c] = fmaxf(lo + bv[c], 0.f);
            if (pg < 6) so[(2 * pg + 1) * 30 + c] = fmaxf(hi + bv[c], 0.f);
        }
    }
}

__global__ __launch_bounds__(512, 1)
void conv5x5_v6(const float* __restrict__ in, const float* __restrict__ w,
                const float* __restrict__ bias, float* __restrict__ out) {
    extern __shared__ float sm[];
    float* sin = sm;            // [3][CONV_SIN] = 27540 (also output stage)
    float* sw  = sm + 27540;    // 22500 weights

    const int tid  = threadIdx.x;
    const int img0 = blockIdx.x * 3;

    for (int i = tid; i < 3 * CONV_SIN; i += 512) sin[i] = 0.f;
    for (int i = tid; i < 22500; i += 512) sw[i] = w[i];
    __syncthreads();
    for (int i = tid; i < 3 * 5070; i += 512) {
        int img = i / 5070, rem = i - img * 5070;
        if (img0 + img < NIMG) {
            int p = rem / 30, ci = rem - p * 30;
            sin[img * CONV_SIN + ci * 306 + (p / 13 + 2) * 18 + (p % 13 + 2)] =
                in[(size_t)(img0 + img) * 5070 + rem];
        }
    }
    __syncthreads();

    const int  half = tid >> 8;            // 0: warps 0-7, 1: warps 8-15
    const int  rr2  = tid & 255;           // tile id, active < 234
    const int  img  = rr2 / 78;
    const int  rr   = rr2 - img * 78;
    const int  orow = rr / 6;
    const int  cog  = rr - orow * 6;
    const int  co0  = cog * 5;
    const bool on   = (rr2 < 234);

    if (half == 0) {
        ull acc[4][5];
        #pragma unroll
        for (int p = 0; p < 4; p++)
            #pragma unroll
            for (int c = 0; c < 5; c++) acc[p][c] = 0ull;
        if (on)
            conv_tile<4>(sin + img * CONV_SIN, sw, orow, co0, 0, acc);
        __syncthreads();   // all reads of sin done; reuse as output stage
        if (on)
            conv_epilogue<4>(sin + img * 5070 + orow * 13 * 30 + co0,
                             bias, co0, 0, acc);
    } else {
        ull acc[3][5];
        #pragma unroll
        for (int p = 0; p < 3; p++)
            #pragma unroll
            for (int c = 0; c < 5; c++) acc[p][c] = 0ull;
        if (on)
            conv_tile<3>(sin + img * CONV_SIN, sw, orow, co0, 8, acc);
        __syncthreads();
        if (on)
            conv_epilogue<3>(sin + img * 5070 + orow * 13 * 30 + co0,
                             bias, co0, 4, acc);
    }

    __syncthreads();
    for (int i = tid; i < 3 * 5070; i += 512) {
        int img2 = i / 5070;
        if (img0 + img2 < NIMG)
            out[(size_t)(img0 + img2) * 5070 + (i - img2 * 5070)] =
                sin[img2 * 5070 + (i - img2 * 5070)];
    }
}

// ---------------- persistent LSTM: all 55 timesteps in one kernel -----------
#define SHP 82
__global__ __launch_bounds__(512, 1)
void lstm_persist(const float* __restrict__ xw, const float* __restrict__ Wh,
                  float* __restrict__ hs) {
    extern __shared__ float sm[];
    float* sW = sm;              // [100][400]
    float* sh = sm + 40000;      // 2 x [100][SHP]
    const int tid  = threadIdx.x;
    const int row0 = blockIdx.x * 74;

    for (int i = tid; i < 40000; i += 512) sW[i] = Wh[i];
    for (int i = tid; i < 2 * 100 * SHP; i += 512) sh[i] = 0.f;
    __syncthreads();

    const int ut = tid % 50;
    const int rt = tid / 50;
    const int u0 = 2 * ut;
    const bool on = tid < 500;

    int  rowg[8];
    bool val[8];
    #pragma unroll
    for (int j = 0; j < 8; j++) {
        int r = rt * 8 + j;
        rowg[j] = row0 + r;
        val[j] = on && (r < 74) && (rowg[j] < NN);
    }
    float cc[8][2];
    #pragma unroll
    for (int j = 0; j < 8; j++) { cc[j][0] = 0.f; cc[j][1] = 0.f; }

    int cur = 0;
    for (int t = 0; t < TSTEPS; t++) {
        const float* xwt = xw + (size_t)t * NN * 400;
        ull acc[8][4];
        #pragma unroll
        for (int j = 0; j < 8; j++) {
            if (val[j]) {
                const float* zr = xwt + (size_t)rowg[j] * 400 + u0;
                #pragma unroll
                for (int g = 0; g < 4; g++)
                    acc[j][g] = *reinterpret_cast<const ull*>(zr + g * 100);
            } else {
                #pragma unroll
                for (int g = 0; g < 4; g++) acc[j][g] = 0ull;
            }
        }

        if (t > 0) {
            const float* shc = sh + cur * (100 * SHP);
            const int rb = rt * 8;
            #pragma unroll 4
            for (int k = 0; k < 100; k++) {
                const float* wk = sW + k * 400 + u0;
                ull wq0 = *reinterpret_cast<const ull*>(wk);
                ull wq1 = *reinterpret_cast<const ull*>(wk + 100);
                ull wq2 = *reinterpret_cast<const ull*>(wk + 200);
                ull wq3 = *reinterpret_cast<const ull*>(wk + 300);
                const float* hv = shc + k * SHP + rb;
                ull hp[4];
                #pragma unroll
                for (int q = 0; q < 4; q++)
                    hp[q] = *reinterpret_cast<const ull*>(&hv[2 * q]);
                #pragma unroll
                for (int q = 0; q < 4; q++) {
                    float he, ho;
                    upk2(hp[q], he, ho);
                    ull ade = pk2(he, he);
                    fma2(acc[2 * q][0], ade, wq0);
                    fma2(acc[2 * q][1], ade, wq1);
                    fma2(acc[2 * q][2], ade, wq2);
                    fma2(acc[2 * q][3], ade, wq3);
                    ull ado = pk2(ho, ho);
                    fma2(acc[2 * q + 1][0], ado, wq0);
                    fma2(acc[2 * q + 1][1], ado, wq1);
                    fma2(acc[2 * q + 1][2], ado, wq2);
                    fma2(acc[2 * q + 1][3], ado, wq3);
                }
            }
        }

        float* shn = sh + (cur ^ 1) * (100 * SHP);
        float* hst = hs + (size_t)t * NN * HL;
        #pragma unroll
        for (int j = 0; j < 8; j++) {
            int r = rt * 8 + j;
            if (on && r < 74) {
                float i0, i1, j0, j1, f0, f1, o0, o1;
                upk2(acc[j][0], i0, i1);
                upk2(acc[j][1], j0, j1);
                upk2(acc[j][2], f0, f1);
                upk2(acc[j][3], o0, o1);
                float c0 = sigm(f0 + 1.f) * cc[j][0] + sigm(i0) * tanha(j0);
                float c1 = sigm(f1 + 1.f) * cc[j][1] + sigm(i1) * tanha(j1);
                cc[j][0] = c0; cc[j][1] = c1;
                float h0 = sigm(o0) * tanha(c0);
                float h1 = sigm(o1) * tanha(c1);
                shn[u0 * SHP + r]       = h0;
                shn[(u0 + 1) * SHP + r] = h1;
                if (rowg[j] < NN)
                    *reinterpret_cast<float2*>(&hst[(size_t)rowg[j] * HL + u0]) =
                        make_float2(h0, h1);
            }
        }
        cur ^= 1;
        __syncthreads();
    }
}

// ---------------- final 1x1 conv (100 -> 1) + output transpose --------------
__global__ void final_proj(const float* __restrict__ hs2, const float* __restrict__ we,
                           const float* __restrict__ be, float* __restrict__ out) {
    long r = (long)blockIdx.x * blockDim.x + threadIdx.x;
    if (r >= (long)NROWS) return;
    int n = (int)(r % NN);
    int l = (int)(r / NN);
    const float4* row = reinterpret_cast<const float4*>(hs2 + (size_t)r * HL);
    const float4* wv  = reinterpret_cast<const float4*>(we);
    float acc = 0.f;
    #pragma unroll
    for (int i = 0; i < 25; i++) {
        float4 v = row[i], w = wv[i];
        acc += v.x * w.x + v.y * w.y + v.z * w.z + v.w * w.w;
    }
    out[(size_t)n * 55 + l] = acc + be[0];
}

// ---------------- host side -------------------------------------------------
extern "C" void kernel_launch(void* const* d_in, const int* in_sizes, int n_in,
                              void* d_out, int out_size) {
    (void)in_sizes; (void)n_in; (void)out_size;
    const float* x = (const float*)d_in[0];
    const float* w1[4] = {(const float*)d_in[1], (const float*)d_in[3],
                          (const float*)d_in[5], (const float*)d_in[7]};
    const float* b1[4] = {(const float*)d_in[2], (const float*)d_in[4],
                          (const float*)d_in[6], (const float*)d_in[8]};
    const float* w2[4] = {(const float*)d_in[9],  (const float*)d_in[11],
                          (const float*)d_in[13], (const float*)d_in[15]};
    const float* b2[4] = {(const float*)d_in[10], (const float*)d_in[12],
                          (const float*)d_in[14], (const float*)d_in[16]};
    const float* lw1 = (const float*)d_in[17];
    const float* lb1 = (const float*)d_in[18];
    const float* lw2 = (const float*)d_in[19];
    const float* lb2 = (const float*)d_in[20];
    const float* we  = (const float*)d_in[21];
    const float* be  = (const float*)d_in[22];
    float* out = (float*)d_out;

    void *p0, *p1, *pxw, *ph1, *ph2;
    cudaGetSymbolAddress(&p0,  g_act0);
    cudaGetSymbolAddress(&p1,  g_act1);
    cudaGetSymbolAddress(&pxw, g_xw);
    cudaGetSymbolAddress(&ph1, g_hs1);
    cudaGetSymbolAddress(&ph2, g_hs2);
    float* act0 = (float*)p0;
    float* act1 = (float*)p1;
    float* xw   = (float*)pxw;
    float* hs1  = (float*)ph1;
    float* hs2  = (float*)ph2;

    const size_t conv_sm  = 50040u * sizeof(float);                     // 200160
    const size_t lstm_sm  = (40000u + 2u * 100u * SHP) * sizeof(float); // 225600
    const size_t c1_sm    = (256u * C1_STG + 3420u + 120u) * sizeof(float); // 47952
    const size_t g30_sm   = (size_t)(30 * 231) * sizeof(float);         // 27720
    const size_t g100_sm  = (size_t)(100 * 231) * sizeof(float);        // 92400

    cudaFuncSetAttribute(conv5x5_v6, cudaFuncAttributeMaxDynamicSharedMemorySize,
                         (int)conv_sm);
    cudaFuncSetAttribute(lstm_persist, cudaFuncAttributeMaxDynamicSharedMemorySize,
                         (int)lstm_sm);
    cudaFuncSetAttribute((const void*)gemm_xw<100>,
                         cudaFuncAttributeMaxDynamicSharedMemorySize, (int)g100_sm);

    // 1) input transpose
    {
        long total = (long)NROWS * 6;
        transpose_in<<<(unsigned)((total + 255) / 256), 256>>>(x, act0);
    }

    // 2) fused 1x1 conv chain (4 layers, one kernel)
    {
        const unsigned grid = (NROWS + 255) / 256;   // 2324
        conv1_fused<<<grid, 128, c1_sm>>>(act0,
                                          w1[0], b1[0], w1[1], b1[1],
                                          w1[2], b1[2], w1[3], b1[3],
                                          act1, NROWS);
    }

    // 3) four 5x5 SAME convs (zero-waste asymmetric p-split)
    {
        const int grid = (NIMG + 2) / 3;   // 1174
        conv5x5_v6<<<grid, 512, conv_sm>>>(act1, w2[0], b2[0], act0);
        conv5x5_v6<<<grid, 512, conv_sm>>>(act0, w2[1], b2[1], act1);
        conv5x5_v6<<<grid, 512, conv_sm>>>(act1, w2[2], b2[2], act0);
        conv5x5_v6<<<grid, 512, conv_sm>>>(act0, w2[3], b2[3], act1);
    }

    const unsigned GY = (NROWS + 127) / 128;   // 4648

    // 4) LSTM layer 1
    gemm_xw<30><<<dim3(4, GY), 320, g30_sm>>>(act1, lw1, lb1, xw, NROWS);
    lstm_persist<<<147, 512, lstm_sm>>>(xw, lw1 + (size_t)30 * 400, hs1);

    //    LSTM layer 2
    gemm_xw<100><<<dim3(4, GY), 320, g100_sm>>>(hs1, lw2, lb2, xw, NROWS);
    lstm_persist<<<147, 512, lstm_sm>>>(xw, lw2 + (size_t)100 * 400, hs2);

    // 5) final projection + output transpose
    final_proj<<<(NROWS + 255) / 256, 256>>>(hs2, we, be, out);
}

// round 11
// speedup vs baseline: 1.0743x; 1.0743x over previous
#include <cuda_runtime.h>
#include <cstdint>

#define NROWS 594880   // 55 * 64 * 169
#define NN    10816    // 64 * 169 rows per timestep
#define TSTEPS 55
#define HL    100
#define NIMG  3520     // 55 * 64 images of 13x13

typedef unsigned long long ull;

// ---------------- f32x2 packed-math helpers (sm_103a FFMA2) -----------------
__device__ __forceinline__ ull pk2(float lo, float hi) {
    ull r; asm("mov.b64 %0,{%1,%2};" : "=l"(r) : "f"(lo), "f"(hi)); return r;
}
__device__ __forceinline__ void upk2(ull v, float& lo, float& hi) {
    asm("mov.b64 {%0,%1},%2;" : "=f"(lo), "=f"(hi) : "l"(v));
}
__device__ __forceinline__ void fma2(ull& d, ull a, ull b) {
    asm("fma.rn.f32x2 %0,%1,%2,%0;" : "+l"(d) : "l"(a), "l"(b));
}

__device__ __forceinline__ float sigm(float x) {
    return __fdividef(1.f, 1.f + __expf(-x));
}
__device__ __forceinline__ float tanha(float x) {
    return __fdividef(2.f, 1.f + __expf(-2.f * x)) - 1.f;
}

// ---------------- static device scratch -------------------------------------
__device__ float g_act0[(size_t)NROWS * 30];
__device__ float g_act1[(size_t)NROWS * 30];
__device__ float g_xw [(size_t)NROWS * 400];
__device__ float g_hs1[(size_t)NROWS * HL];
__device__ float g_hs2[(size_t)NROWS * HL];

// ---------------- input transpose: [B,13,13,L,C] -> [(l*64+b)*169+pix, 24] --
__global__ void transpose_in(const float* __restrict__ x, float* __restrict__ y) {
    long idx = (long)blockIdx.x * blockDim.x + threadIdx.x;
    const long total = (long)NROWS * 6;
    if (idx >= total) return;
    int  c4  = (int)(idx % 6);
    long row = idx / 6;
    int  pix = (int)(row % 169);
    long t1  = row / 169;
    int  b   = (int)(t1 % 64);
    int  l   = (int)(t1 / 64);
    long src = (((long)(b * 169 + pix)) * 55 + l) * 24 + c4 * 4;
    reinterpret_cast<float4*>(y)[row * 6 + c4] =
        *reinterpret_cast<const float4*>(x + src);
}

// ---------------- fused 1x1 conv chain: 4 layers, activations in registers --
#define C1_STG 33
__global__ __launch_bounds__(128, 3)
void conv1_fused(const float* __restrict__ A,
                 const float* __restrict__ w0, const float* __restrict__ b0,
                 const float* __restrict__ w1, const float* __restrict__ b1,
                 const float* __restrict__ w2, const float* __restrict__ b2,
                 const float* __restrict__ w3, const float* __restrict__ b3,
                 float* __restrict__ Cout, long M) {
    extern __shared__ float sm[];
    float* stage = sm;                 // [256][33], scalar access only
    float* sw    = sm + 256 * C1_STG;  // 720 + 3*900 = 3420 (base even: 8448)
    float* sb    = sw + 3420;          // 4 x 30

    const int tid  = threadIdx.x;
    const long row0 = (long)blockIdx.x * 256;

    for (int i = tid; i < 720; i += 128) sw[i] = w0[i];
    for (int i = tid; i < 900; i += 128) {
        sw[720 + i]  = w1[i];
        sw[1620 + i] = w2[i];
        sw[2520 + i] = w3[i];
    }
    if (tid < 30) {
        sb[tid] = b0[tid]; sb[30 + tid] = b1[tid];
        sb[60 + tid] = b2[tid]; sb[90 + tid] = b3[tid];
    }
    for (int f = tid; f < 1536; f += 128) {
        int r = f / 6, c4 = f - r * 6;
        long gr = row0 + r;
        float4 v = make_float4(0.f, 0.f, 0.f, 0.f);
        if (gr < M) v = *reinterpret_cast<const float4*>(A + gr * 24 + 4 * c4);
        float* d = &stage[r * C1_STG + 4 * c4];
        d[0] = v.x; d[1] = v.y; d[2] = v.z; d[3] = v.w;
    }
    __syncthreads();

    float a0[30], a1[30];
    {
        const float* s0 = &stage[(2 * tid) * C1_STG];
        const float* s1 = &stage[(2 * tid + 1) * C1_STG];
        #pragma unroll
        for (int k = 0; k < 24; k++) { a0[k] = s0[k]; a1[k] = s1[k]; }
    }

    ull acc0[15], acc1[15];
    #pragma unroll 1
    for (int layer = 0; layer < 4; layer++) {
        const int K = (layer == 0) ? 24 : 30;
        const float* wl = sw + ((layer == 0) ? 0 : 720 + (layer - 1) * 900);
        const float* bl = sb + layer * 30;
        #pragma unroll
        for (int p = 0; p < 15; p++) { acc0[p] = 0ull; acc1[p] = 0ull; }
        #pragma unroll 6
        for (int k = 0; k < K; k++) {
            ull ad0 = pk2(a0[k], a0[k]);
            ull ad1 = pk2(a1[k], a1[k]);
            const ull* wk = reinterpret_cast<const ull*>(&wl[k * 30]);
            #pragma unroll
            for (int p = 0; p < 15; p++) {
                ull bv = wk[p];
                fma2(acc0[p], ad0, bv);
                fma2(acc1[p], ad1, bv);
            }
        }
        #pragma unroll
        for (int p = 0; p < 15; p++) {
            float l0, h0, l1, h1;
            upk2(acc0[p], l0, h0);
            upk2(acc1[p], l1, h1);
            float be = bl[2 * p], bo = bl[2 * p + 1];
            a0[2 * p]     = fmaxf(l0 + be, 0.f);
            a0[2 * p + 1] = fmaxf(h0 + bo, 0.f);
            a1[2 * p]     = fmaxf(l1 + be, 0.f);
            a1[2 * p + 1] = fmaxf(h1 + bo, 0.f);
        }
    }

    __syncthreads();
    {
        float* s0 = &stage[(2 * tid) * C1_STG];
        float* s1 = &stage[(2 * tid + 1) * C1_STG];
        #pragma unroll
        for (int k = 0; k < 30; k++) { s0[k] = a0[k]; s1[k] = a1[k]; }
    }
    __syncthreads();
    for (int f = tid; f < 256 * 15; f += 128) {
        int r = f / 15, c2 = f - r * 15;
        long gr = row0 + r;
        if (gr < M) {
            const float* s = &stage[r * C1_STG + 2 * c2];
            *reinterpret_cast<float2*>(&Cout[gr * 30 + 2 * c2]) =
                make_float2(s[0], s[1]);
        }
    }
}

// ---------------- bulk LSTM x-projection GEMM: C = A[M,K]@B[K,400] + bias ---
template<int K>
__global__ __launch_bounds__(320, 2)
void gemm_xw(const float* __restrict__ A, const float* __restrict__ B,
             const float* __restrict__ bias, float* __restrict__ C, long M) {
    constexpr int BM = 128, BN = 100, AS = BM + 3;   // 131
    extern __shared__ float sm[];
    float* Asm = sm;                 // [K][AS]
    float* Bsm = sm + K * AS;        // [K][BN]
    float* stg = sm;                 // alias (post-sync), stride 101, scalar

    const int tid = threadIdx.x;
    const int tc = tid / 32, tr = tid % 32;
    const long row0 = (long)blockIdx.y * BM;
    const int  col0 = blockIdx.x * BN;

    for (int i = tid; i < BM * K; i += 320) {
        int r = i / K, k = i - r * K;
        long gr = row0 + r;
        Asm[k * AS + r] = (gr < M) ? A[gr * (long)K + k] : 0.f;
    }
    for (int i = tid; i < K * BN; i += 320) {
        int k = i / BN, n = i - k * BN;
        Bsm[i] = B[(size_t)k * 400 + col0 + n];
    }
    __syncthreads();

    const int cbase = tc * 10;
    ull acc[4][5];
    #pragma unroll
    for (int j = 0; j < 4; j++)
        #pragma unroll
        for (int p = 0; p < 5; p++) acc[j][p] = 0ull;

    #pragma unroll 10
    for (int k = 0; k < K; k++) {
        ull bv[5];
        #pragma unroll
        for (int p = 0; p < 5; p++)
            bv[p] = *reinterpret_cast<const ull*>(&Bsm[k * BN + cbase + 2 * p]);
        const float* ar = &Asm[k * AS + tr];
        #pragma unroll
        for (int j = 0; j < 4; j++) {
            float a = ar[32 * j];
            ull ad = pk2(a, a);
            #pragma unroll
            for (int p = 0; p < 5; p++) fma2(acc[j][p], ad, bv[p]);
        }
    }

    float bl[5], bh[5];
    #pragma unroll
    for (int p = 0; p < 5; p++) {
        bl[p] = bias[col0 + cbase + 2 * p];
        bh[p] = bias[col0 + cbase + 2 * p + 1];
    }

    #pragma unroll 1
    for (int ch = 0; ch < 2; ch++) {
        __syncthreads();
        #pragma unroll
        for (int jj = 0; jj < 2; jj++) {
            int j = ch * 2 + jj;
            int rl = jj * 32 + tr;
            float* sr = &stg[rl * 101 + cbase];
            #pragma unroll
            for (int p = 0; p < 5; p++) {
                float lo, hi;
                upk2(acc[j][p], lo, hi);
                sr[2 * p]     = lo + bl[p];
                sr[2 * p + 1] = hi + bh[p];
            }
        }
        __syncthreads();
        for (int i = tid; i < 64 * 50; i += 320) {
            int r = i / 50, c2 = i - r * 50;
            long gr = row0 + ch * 64 + r;
            if (gr < M) {
                const float* s = &stg[r * 101 + 2 * c2];
                *reinterpret_cast<float2*>(&C[gr * 400 + col0 + 2 * c2]) =
                    make_float2(s[0], s[1]);
            }
        }
    }
}

// ---------------- 5x5 SAME conv v7: cout-pair-packed accumulators -----------
// Key change vs v6: acc lanes = adjacent cout pair -> weights load as direct
// LDS.64 (warp-uniform broadcast), ZERO weight-dup movs. Input scalar dup'd
// 9x per (ci,ki), amortized over 25 taps. Thread = (cog of 10 couts, img,
// orow, pixel-quint p0=5*pg). acc[5 pix][5 co-pairs]. Pixels 13,14 masked in
// epilogue (benign smem overread feeds only masked lanes).
#define CONV_SIN 9180   // 30 * 17 * 18
__device__ __forceinline__ void conv_tile7(const float* __restrict__ vbase,
                                           const float* __restrict__ sw,
                                           int orow, int co0, ull (&acc)[5][5]) {
    #pragma unroll 2
    for (int ci = 0; ci < 30; ci++) {
        const float* bci = vbase + ci * 306;
        #pragma unroll 1
        for (int ki = 0; ki < 5; ki++) {
            const float* vrow = bci + (orow + ki) * 18;
            ull dup[9];
            #pragma unroll
            for (int q = 0; q < 9; q++) {
                float t = vrow[q];
                dup[q] = pk2(t, t);
            }
            #pragma unroll
            for (int kj = 0; kj < 5; kj++) {
                const ull* wq = reinterpret_cast<const ull*>(
                    sw + ((ki * 5 + kj) * 30 + ci) * 30 + co0);   // even offs
                ull w0 = wq[0], w1 = wq[1], w2 = wq[2], w3 = wq[3], w4 = wq[4];
                #pragma unroll
                for (int pp = 0; pp < 5; pp++) {
                    ull a = dup[pp + kj];
                    fma2(acc[pp][0], a, w0);
                    fma2(acc[pp][1], a, w1);
                    fma2(acc[pp][2], a, w2);
                    fma2(acc[pp][3], a, w3);
                    fma2(acc[pp][4], a, w4);
                }
            }
        }
    }
}

__global__ __launch_bounds__(512, 1)
void conv5x5_v7(const float* __restrict__ in, const float* __restrict__ w,
                const float* __restrict__ bias, float* __restrict__ out) {
    extern __shared__ float sm[];
    float* sin = sm;            // [3][CONV_SIN] = 27540 (also output stage)
    float* sw  = sm + 27540;    // 22500 weights (scalar)

    const int tid  = threadIdx.x;
    const int img0 = blockIdx.x * 3;

    for (int i = tid; i < 3 * CONV_SIN; i += 512) sin[i] = 0.f;
    for (int i = tid; i < 22500; i += 512) sw[i] = w[i];
    __syncthreads();
    for (int i = tid; i < 3 * 5070; i += 512) {
        int img = i / 5070, rem = i - img * 5070;
        if (img0 + img < NIMG) {
            int p = rem / 30, ci = rem - p * 30;
            sin[img * CONV_SIN + ci * 306 + (p / 13 + 2) * 18 + (p % 13 + 2)] =
                in[(size_t)(img0 + img) * 5070 + rem];
        }
    }
    __syncthreads();

    // tile mapping, cog slowest so weight LDS.64 is warp-uniform
    const int  cog  = tid / 117;           // 0..2 (3 = inactive tail)
    const int  rem  = tid - cog * 117;
    const int  img  = rem / 39;
    const int  rem2 = rem - img * 39;
    const int  orow = rem2 / 3;
    const int  pg   = rem2 - orow * 3;
    const int  co0  = cog * 10;
    const int  p0   = pg * 5;              // pixels p0..p0+4 (13,14 masked)
    const bool on   = (tid < 351);

    ull acc[5][5];
    #pragma unroll
    for (int p = 0; p < 5; p++)
        #pragma unroll
        for (int c = 0; c < 5; c++) acc[p][c] = 0ull;

    if (on)
        conv_tile7(sin + img * CONV_SIN + p0, sw, orow, co0, acc);

    __syncthreads();   // all reads of sin/sw-region done; reuse sin as stage
    if (on) {
        float bl[5], bh[5];
        #pragma unroll
        for (int c = 0; c < 5; c++) {
            bl[c] = bias[co0 + 2 * c];
            bh[c] = bias[co0 + 2 * c + 1];
        }
        float* so = sin + img * 5070 + orow * 390;
        #pragma unroll
        for (int pp = 0; pp < 5; pp++) {
            int p = p0 + pp;
            if (p < 13) {
                float* sp = so + p * 30 + co0;
                #pragma unroll
                for (int c = 0; c < 5; c++) {
                    float lo, hi;
                    upk2(acc[pp][c], lo, hi);
                    sp[2 * c]     = fmaxf(lo + bl[c], 0.f);
                    sp[2 * c + 1] = fmaxf(hi + bh[c], 0.f);
                }
            }
        }
    }
    __syncthreads();
    for (int i = tid; i < 3 * 5070; i += 512) {
        int img2 = i / 5070;
        if (img0 + img2 < NIMG)
            out[(size_t)(img0 + img2) * 5070 + (i - img2 * 5070)] =
                sin[img2 * 5070 + (i - img2 * 5070)];
    }
}

// ---------------- persistent LSTM: all 55 timesteps in one kernel -----------
#define SHP 82
__global__ __launch_bounds__(512, 1)
void lstm_persist(const float* __restrict__ xw, const float* __restrict__ Wh,
                  float* __restrict__ hs) {
    extern __shared__ float sm[];
    float* sW = sm;              // [100][400]
    float* sh = sm + 40000;      // 2 x [100][SHP]
    const int tid  = threadIdx.x;
    const int row0 = blockIdx.x * 74;

    for (int i = tid; i < 40000; i += 512) sW[i] = Wh[i];
    for (int i = tid; i < 2 * 100 * SHP; i += 512) sh[i] = 0.f;
    __syncthreads();

    const int ut = tid % 50;
    const int rt = tid / 50;
    const int u0 = 2 * ut;
    const bool on = tid < 500;

    int  rowg[8];
    bool val[8];
    #pragma unroll
    for (int j = 0; j < 8; j++) {
        int r = rt * 8 + j;
        rowg[j] = row0 + r;
        val[j] = on && (r < 74) && (rowg[j] < NN);
    }
    float cc[8][2];
    #pragma unroll
    for (int j = 0; j < 8; j++) { cc[j][0] = 0.f; cc[j][1] = 0.f; }

    int cur = 0;
    for (int t = 0; t < TSTEPS; t++) {
        const float* xwt = xw + (size_t)t * NN * 400;
        ull acc[8][4];
        #pragma unroll
        for (int j = 0; j < 8; j++) {
            if (val[j]) {
                const float* zr = xwt + (size_t)rowg[j] * 400 + u0;
                #pragma unroll
                for (int g = 0; g < 4; g++)
                    acc[j][g] = *reinterpret_cast<const ull*>(zr + g * 100);
            } else {
                #pragma unroll
                for (int g = 0; g < 4; g++) acc[j][g] = 0ull;
            }
        }

        if (t > 0) {
            const float* shc = sh + cur * (100 * SHP);
            const int rb = rt * 8;
            #pragma unroll 4
            for (int k = 0; k < 100; k++) {
                const float* wk = sW + k * 400 + u0;
                ull wq0 = *reinterpret_cast<const ull*>(wk);
                ull wq1 = *reinterpret_cast<const ull*>(wk + 100);
                ull wq2 = *reinterpret_cast<const ull*>(wk + 200);
                ull wq3 = *reinterpret_cast<const ull*>(wk + 300);
                const float* hv = shc + k * SHP + rb;
                ull hp[4];
                #pragma unroll
                for (int q = 0; q < 4; q++)
                    hp[q] = *reinterpret_cast<const ull*>(&hv[2 * q]);
                #pragma unroll
                for (int q = 0; q < 4; q++) {
                    float he, ho;
                    upk2(hp[q], he, ho);
                    ull ade = pk2(he, he);
                    fma2(acc[2 * q][0], ade, wq0);
                    fma2(acc[2 * q][1], ade, wq1);
                    fma2(acc[2 * q][2], ade, wq2);
                    fma2(acc[2 * q][3], ade, wq3);
                    ull ado = pk2(ho, ho);
                    fma2(acc[2 * q + 1][0], ado, wq0);
                    fma2(acc[2 * q + 1][1], ado, wq1);
                    fma2(acc[2 * q + 1][2], ado, wq2);
                    fma2(acc[2 * q + 1][3], ado, wq3);
                }
            }
        }

        float* shn = sh + (cur ^ 1) * (100 * SHP);
        float* hst = hs + (size_t)t * NN * HL;
        #pragma unroll
        for (int j = 0; j < 8; j++) {
            int r = rt * 8 + j;
            if (on && r < 74) {
                float i0, i1, j0, j1, f0, f1, o0, o1;
                upk2(acc[j][0], i0, i1);
                upk2(acc[j][1], j0, j1);
                upk2(acc[j][2], f0, f1);
                upk2(acc[j][3], o0, o1);
                float c0 = sigm(f0 + 1.f) * cc[j][0] + sigm(i0) * tanha(j0);
                float c1 = sigm(f1 + 1.f) * cc[j][1] + sigm(i1) * tanha(j1);
                cc[j][0] = c0; cc[j][1] = c1;
                float h0 = sigm(o0) * tanha(c0);
                float h1 = sigm(o1) * tanha(c1);
                shn[u0 * SHP + r]       = h0;
                shn[(u0 + 1) * SHP + r] = h1;
                if (rowg[j] < NN)
                    *reinterpret_cast<float2*>(&hst[(size_t)rowg[j] * HL + u0]) =
                        make_float2(h0, h1);
            }
        }
        cur ^= 1;
        __syncthreads();
    }
}

// ---------------- final 1x1 conv (100 -> 1) + output transpose --------------
__global__ void final_proj(const float* __restrict__ hs2, const float* __restrict__ we,
                           const float* __restrict__ be, float* __restrict__ out) {
    long r = (long)blockIdx.x * blockDim.x + threadIdx.x;
    if (r >= (long)NROWS) return;
    int n = (int)(r % NN);
    int l = (int)(r / NN);
    const float4* row = reinterpret_cast<const float4*>(hs2 + (size_t)r * HL);
    const float4* wv  = reinterpret_cast<const float4*>(we);
    float acc = 0.f;
    #pragma unroll
    for (int i = 0; i < 25; i++) {
        float4 v = row[i], w = wv[i];
        acc += v.x * w.x + v.y * w.y + v.z * w.z + v.w * w.w;
    }
    out[(size_t)n * 55 + l] = acc + be[0];
}

// ---------------- host side -------------------------------------------------
extern "C" void kernel_launch(void* const* d_in, const int* in_sizes, int n_in,
                              void* d_out, int out_size) {
    (void)in_sizes; (void)n_in; (void)out_size;
    const float* x = (const float*)d_in[0];
    const float* w1[4] = {(const float*)d_in[1], (const float*)d_in[3],
                          (const float*)d_in[5], (const float*)d_in[7]};
    const float* b1[4] = {(const float*)d_in[2], (const float*)d_in[4],
                          (const float*)d_in[6], (const float*)d_in[8]};
    const float* w2[4] = {(const float*)d_in[9],  (const float*)d_in[11],
                          (const float*)d_in[13], (const float*)d_in[15]};
    const float* b2[4] = {(const float*)d_in[10], (const float*)d_in[12],
                          (const float*)d_in[14], (const float*)d_in[16]};
    const float* lw1 = (const float*)d_in[17];
    const float* lb1 = (const float*)d_in[18];
    const float* lw2 = (const float*)d_in[19];
    const float* lb2 = (const float*)d_in[20];
    const float* we  = (const float*)d_in[21];
    const float* be  = (const float*)d_in[22];
    float* out = (float*)d_out;

    void *p0, *p1, *pxw, *ph1, *ph2;
    cudaGetSymbolAddress(&p0,  g_act0);
    cudaGetSymbolAddress(&p1,  g_act1);
    cudaGetSymbolAddress(&pxw, g_xw);
    cudaGetSymbolAddress(&ph1, g_hs1);
    cudaGetSymbolAddress(&ph2, g_hs2);
    float* act0 = (float*)p0;
    float* act1 = (float*)p1;
    float* xw   = (float*)pxw;
    float* hs1  = (float*)ph1;
    float* hs2  = (float*)ph2;

    const size_t conv_sm  = 50040u * sizeof(float);                     // 200160
    const size_t lstm_sm  = (40000u + 2u * 100u * SHP) * sizeof(float); // 225600
    const size_t c1_sm    = (256u * C1_STG + 3420u + 120u) * sizeof(float); // 47952
    const size_t g30_sm   = (size_t)(30 * 231) * sizeof(float);         // 27720
    const size_t g100_sm  = (size_t)(100 * 231) * sizeof(float);        // 92400

    cudaFuncSetAttribute(conv5x5_v7, cudaFuncAttributeMaxDynamicSharedMemorySize,
                         (int)conv_sm);
    cudaFuncSetAttribute(lstm_persist, cudaFuncAttributeMaxDynamicSharedMemorySize,
                         (int)lstm_sm);
    cudaFuncSetAttribute((const void*)gemm_xw<100>,
                         cudaFuncAttributeMaxDynamicSharedMemorySize, (int)g100_sm);

    // 1) input transpose
    {
        long total = (long)NROWS * 6;
        transpose_in<<<(unsigned)((total + 255) / 256), 256>>>(x, act0);
    }

    // 2) fused 1x1 conv chain (4 layers, one kernel)
    {
        const unsigned grid = (NROWS + 255) / 256;   // 2324
        conv1_fused<<<grid, 128, c1_sm>>>(act0,
                                          w1[0], b1[0], w1[1], b1[1],
                                          w1[2], b1[2], w1[3], b1[3],
                                          act1, NROWS);
    }

    // 3) four 5x5 SAME convs (cout-pair-packed accumulators)
    {
        const int grid = (NIMG + 2) / 3;   // 1174
        conv5x5_v7<<<grid, 512, conv_sm>>>(act1, w2[0], b2[0], act0);
        conv5x5_v7<<<grid, 512, conv_sm>>>(act0, w2[1], b2[1], act1);
        conv5x5_v7<<<grid, 512, conv_sm>>>(act1, w2[2], b2[2], act0);
        conv5x5_v7<<<grid, 512, conv_sm>>>(act0, w2[3], b2[3], act1);
    }

    const unsigned GY = (NROWS + 127) / 128;   // 4648

    // 4) LSTM layer 1
    gemm_xw<30><<<dim3(4, GY), 320, g30_sm>>>(act1, lw1, lb1, xw, NROWS);
    lstm_persist<<<147, 512, lstm_sm>>>(xw, lw1 + (size_t)30 * 400, hs1);

    //    LSTM layer 2
    gemm_xw<100><<<dim3(4, GY), 320, g100_sm>>>(hs1, lw2, lb2, xw, NROWS);
    lstm_persist<<<147, 512, lstm_sm>>>(xw, lw2 + (size_t)100 * 400, hs2);

    // 5) final projection + output transpose
    final_proj<<<(NROWS + 255) / 256, 256>>>(hs2, we, be, out);
}

// round 12
// speedup vs baseline: 1.0888x; 1.0134x over previous
#include <cuda_runtime.h>
#include <cstdint>

#define NROWS 594880   // 55 * 64 * 169
#define NN    10816    // 64 * 169 rows per timestep
#define TSTEPS 55
#define HL    100
#define NIMG  3520     // 55 * 64 images of 13x13

typedef unsigned long long ull;

// ---------------- f32x2 packed-math helpers (sm_103a FFMA2) -----------------
__device__ __forceinline__ ull pk2(float lo, float hi) {
    ull r; asm("mov.b64 %0,{%1,%2};" : "=l"(r) : "f"(lo), "f"(hi)); return r;
}
__device__ __forceinline__ void upk2(ull v, float& lo, float& hi) {
    asm("mov.b64 {%0,%1},%2;" : "=f"(lo), "=f"(hi) : "l"(v));
}
__device__ __forceinline__ void fma2(ull& d, ull a, ull b) {
    asm("fma.rn.f32x2 %0,%1,%2,%0;" : "+l"(d) : "l"(a), "l"(b));
}

__device__ __forceinline__ float sigm(float x) {
    return __fdividef(1.f, 1.f + __expf(-x));
}
__device__ __forceinline__ float tanha(float x) {
    return __fdividef(2.f, 1.f + __expf(-2.f * x)) - 1.f;
}

// ---------------- static device scratch -------------------------------------
__device__ float g_act0[(size_t)NROWS * 30];
__device__ float g_act1[(size_t)NROWS * 30];
__device__ float g_xw [(size_t)NROWS * 400];
__device__ float g_hs1[(size_t)NROWS * HL];
__device__ float g_hs2[(size_t)NROWS * HL];

// ---------------- input transpose: [B,13,13,L,C] -> [(l*64+b)*169+pix, 24] --
__global__ void transpose_in(const float* __restrict__ x, float* __restrict__ y) {
    long idx = (long)blockIdx.x * blockDim.x + threadIdx.x;
    const long total = (long)NROWS * 6;
    if (idx >= total) return;
    int  c4  = (int)(idx % 6);
    long row = idx / 6;
    int  pix = (int)(row % 169);
    long t1  = row / 169;
    int  b   = (int)(t1 % 64);
    int  l   = (int)(t1 / 64);
    long src = (((long)(b * 169 + pix)) * 55 + l) * 24 + c4 * 4;
    reinterpret_cast<float4*>(y)[row * 6 + c4] =
        *reinterpret_cast<const float4*>(x + src);
}

// ---------------- fused 1x1 conv chain: 4 layers, activations in registers --
#define C1_STG 33
__global__ __launch_bounds__(128, 3)
void conv1_fused(const float* __restrict__ A,
                 const float* __restrict__ w0, const float* __restrict__ b0,
                 const float* __restrict__ w1, const float* __restrict__ b1,
                 const float* __restrict__ w2, const float* __restrict__ b2,
                 const float* __restrict__ w3, const float* __restrict__ b3,
                 float* __restrict__ Cout, long M) {
    extern __shared__ float sm[];
    float* stage = sm;                 // [256][33], scalar access only
    float* sw    = sm + 256 * C1_STG;  // 720 + 3*900 = 3420 (base even: 8448)
    float* sb    = sw + 3420;          // 4 x 30

    const int tid  = threadIdx.x;
    const long row0 = (long)blockIdx.x * 256;

    for (int i = tid; i < 720; i += 128) sw[i] = w0[i];
    for (int i = tid; i < 900; i += 128) {
        sw[720 + i]  = w1[i];
        sw[1620 + i] = w2[i];
        sw[2520 + i] = w3[i];
    }
    if (tid < 30) {
        sb[tid] = b0[tid]; sb[30 + tid] = b1[tid];
        sb[60 + tid] = b2[tid]; sb[90 + tid] = b3[tid];
    }
    for (int f = tid; f < 1536; f += 128) {
        int r = f / 6, c4 = f - r * 6;
        long gr = row0 + r;
        float4 v = make_float4(0.f, 0.f, 0.f, 0.f);
        if (gr < M) v = *reinterpret_cast<const float4*>(A + gr * 24 + 4 * c4);
        float* d = &stage[r * C1_STG + 4 * c4];
        d[0] = v.x; d[1] = v.y; d[2] = v.z; d[3] = v.w;
    }
    __syncthreads();

    float a0[30], a1[30];
    {
        const float* s0 = &stage[(2 * tid) * C1_STG];
        const float* s1 = &stage[(2 * tid + 1) * C1_STG];
        #pragma unroll
        for (int k = 0; k < 24; k++) { a0[k] = s0[k]; a1[k] = s1[k]; }
    }

    ull acc0[15], acc1[15];
    #pragma unroll 1
    for (int layer = 0; layer < 4; layer++) {
        const int K = (layer == 0) ? 24 : 30;
        const float* wl = sw + ((layer == 0) ? 0 : 720 + (layer - 1) * 900);
        const float* bl = sb + layer * 30;
        #pragma unroll
        for (int p = 0; p < 15; p++) { acc0[p] = 0ull; acc1[p] = 0ull; }
        #pragma unroll 6
        for (int k = 0; k < K; k++) {
            ull ad0 = pk2(a0[k], a0[k]);
            ull ad1 = pk2(a1[k], a1[k]);
            const ull* wk = reinterpret_cast<const ull*>(&wl[k * 30]);
            #pragma unroll
            for (int p = 0; p < 15; p++) {
                ull bv = wk[p];
                fma2(acc0[p], ad0, bv);
                fma2(acc1[p], ad1, bv);
            }
        }
        #pragma unroll
        for (int p = 0; p < 15; p++) {
            float l0, h0, l1, h1;
            upk2(acc0[p], l0, h0);
            upk2(acc1[p], l1, h1);
            float be = bl[2 * p], bo = bl[2 * p + 1];
            a0[2 * p]     = fmaxf(l0 + be, 0.f);
            a0[2 * p + 1] = fmaxf(h0 + bo, 0.f);
            a1[2 * p]     = fmaxf(l1 + be, 0.f);
            a1[2 * p + 1] = fmaxf(h1 + bo, 0.f);
        }
    }

    __syncthreads();
    {
        float* s0 = &stage[(2 * tid) * C1_STG];
        float* s1 = &stage[(2 * tid + 1) * C1_STG];
        #pragma unroll
        for (int k = 0; k < 30; k++) { s0[k] = a0[k]; s1[k] = a1[k]; }
    }
    __syncthreads();
    for (int f = tid; f < 256 * 15; f += 128) {
        int r = f / 15, c2 = f - r * 15;
        long gr = row0 + r;
        if (gr < M) {
            const float* s = &stage[r * C1_STG + 2 * c2];
            *reinterpret_cast<float2*>(&Cout[gr * 30 + 2 * c2]) =
                make_float2(s[0], s[1]);
        }
    }
}

// ---------------- bulk LSTM x-projection GEMM: C = A[M,K]@B[K,400] + bias ---
template<int K>
__global__ __launch_bounds__(320, 2)
void gemm_xw(const float* __restrict__ A, const float* __restrict__ B,
             const float* __restrict__ bias, float* __restrict__ C, long M) {
    constexpr int BM = 128, BN = 100, AS = BM + 3;   // 131
    extern __shared__ float sm[];
    float* Asm = sm;                 // [K][AS]
    float* Bsm = sm + K * AS;        // [K][BN]
    float* stg = sm;                 // alias (post-sync), stride 101, scalar

    const int tid = threadIdx.x;
    const int tc = tid / 32, tr = tid % 32;
    const long row0 = (long)blockIdx.y * BM;
    const int  col0 = blockIdx.x * BN;

    for (int i = tid; i < BM * K; i += 320) {
        int r = i / K, k = i - r * K;
        long gr = row0 + r;
        Asm[k * AS + r] = (gr < M) ? A[gr * (long)K + k] : 0.f;
    }
    for (int i = tid; i < K * BN; i += 320) {
        int k = i / BN, n = i - k * BN;
        Bsm[i] = B[(size_t)k * 400 + col0 + n];
    }
    __syncthreads();

    const int cbase = tc * 10;
    ull acc[4][5];
    #pragma unroll
    for (int j = 0; j < 4; j++)
        #pragma unroll
        for (int p = 0; p < 5; p++) acc[j][p] = 0ull;

    #pragma unroll 10
    for (int k = 0; k < K; k++) {
        ull bv[5];
        #pragma unroll
        for (int p = 0; p < 5; p++)
            bv[p] = *reinterpret_cast<const ull*>(&Bsm[k * BN + cbase + 2 * p]);
        const float* ar = &Asm[k * AS + tr];
        #pragma unroll
        for (int j = 0; j < 4; j++) {
            float a = ar[32 * j];
            ull ad = pk2(a, a);
            #pragma unroll
            for (int p = 0; p < 5; p++) fma2(acc[j][p], ad, bv[p]);
        }
    }

    float bl[5], bh[5];
    #pragma unroll
    for (int p = 0; p < 5; p++) {
        bl[p] = bias[col0 + cbase + 2 * p];
        bh[p] = bias[col0 + cbase + 2 * p + 1];
    }

    #pragma unroll 1
    for (int ch = 0; ch < 2; ch++) {
        __syncthreads();
        #pragma unroll
        for (int jj = 0; jj < 2; jj++) {
            int j = ch * 2 + jj;
            int rl = jj * 32 + tr;
            float* sr = &stg[rl * 101 + cbase];
            #pragma unroll
            for (int p = 0; p < 5; p++) {
                float lo, hi;
                upk2(acc[j][p], lo, hi);
                sr[2 * p]     = lo + bl[p];
                sr[2 * p + 1] = hi + bh[p];
            }
        }
        __syncthreads();
        for (int i = tid; i < 64 * 50; i += 320) {
            int r = i / 50, c2 = i - r * 50;
            long gr = row0 + ch * 64 + r;
            if (gr < M) {
                const float* s = &stg[r * 101 + 2 * c2];
                *reinterpret_cast<float2*>(&C[gr * 400 + col0 + 2 * c2]) =
                    make_float2(s[0], s[1]);
            }
        }
    }
}

// ---------------- 5x5 SAME conv v8: P=4 pixels/thread, 468 active threads ---
// Same co-pair packing / direct LDS.64 weights as v7, but smaller pixel tile:
// pg in {0..3}, p0=4*pg, pixels >=13 masked in epilogue only. 468/512 active
// -> 14.6 warps (was 11) = 3.66/SMSP issue cover. FMA order per output
// unchanged (ci -> ki -> kj).
#define CONV_SIN 9180   // 30 * 17 * 18
__device__ __forceinline__ void conv_tile8(const float* __restrict__ vbase,
                                           const float* __restrict__ sw,
                                           int orow, int co0, ull (&acc)[4][5]) {
    #pragma unroll 2
    for (int ci = 0; ci < 30; ci++) {
        const float* bci = vbase + ci * 306;
        #pragma unroll 1
        for (int ki = 0; ki < 5; ki++) {
            const float* vrow = bci + (orow + ki) * 18;
            ull dup[8];
            #pragma unroll
            for (int q = 0; q < 8; q++) {
                float t = vrow[q];
                dup[q] = pk2(t, t);
            }
            #pragma unroll
            for (int kj = 0; kj < 5; kj++) {
                const ull* wq = reinterpret_cast<const ull*>(
                    sw + ((ki * 5 + kj) * 30 + ci) * 30 + co0);   // even offs
                ull w0 = wq[0], w1 = wq[1], w2 = wq[2], w3 = wq[3], w4 = wq[4];
                #pragma unroll
                for (int pp = 0; pp < 4; pp++) {
                    ull a = dup[pp + kj];
                    fma2(acc[pp][0], a, w0);
                    fma2(acc[pp][1], a, w1);
                    fma2(acc[pp][2], a, w2);
                    fma2(acc[pp][3], a, w3);
                    fma2(acc[pp][4], a, w4);
                }
            }
        }
    }
}

__global__ __launch_bounds__(512, 1)
void conv5x5_v8(const float* __restrict__ in, const float* __restrict__ w,
                const float* __restrict__ bias, float* __restrict__ out) {
    extern __shared__ float sm[];
    float* sin = sm;            // [3][CONV_SIN] = 27540 (also output stage)
    float* sw  = sm + 27540;    // 22500 weights (scalar)

    const int tid  = threadIdx.x;
    const int img0 = blockIdx.x * 3;

    for (int i = tid; i < 3 * CONV_SIN; i += 512) sin[i] = 0.f;
    for (int i = tid; i < 22500; i += 512) sw[i] = w[i];
    __syncthreads();
    for (int i = tid; i < 3 * 5070; i += 512) {
        int img = i / 5070, rem = i - img * 5070;
        if (img0 + img < NIMG) {
            int p = rem / 30, ci = rem - p * 30;
            sin[img * CONV_SIN + ci * 306 + (p / 13 + 2) * 18 + (p % 13 + 2)] =
                in[(size_t)(img0 + img) * 5070 + rem];
        }
    }
    __syncthreads();

    // mapping: cog slowest (weight LDS near-uniform per warp), pg fastest
    const int  cog  = tid / 156;           // 0..2 (tid>=468 inactive)
    const int  rem  = tid - cog * 156;
    const int  img  = rem / 52;
    const int  rem2 = rem - img * 52;
    const int  orow = rem2 / 4;
    const int  pg   = rem2 & 3;
    const int  co0  = cog * 10;
    const int  p0   = pg * 4;              // pixels p0..p0+3 (>=13 masked)
    const bool on   = (tid < 468);

    ull acc[4][5];
    #pragma unroll
    for (int p = 0; p < 4; p++)
        #pragma unroll
        for (int c = 0; c < 5; c++) acc[p][c] = 0ull;

    if (on)
        conv_tile8(sin + img * CONV_SIN + p0, sw, orow, co0, acc);

    __syncthreads();   // all reads of sin/sw done; reuse sin as stage
    if (on) {
        float bl[5], bh[5];
        #pragma unroll
        for (int c = 0; c < 5; c++) {
            bl[c] = bias[co0 + 2 * c];
            bh[c] = bias[co0 + 2 * c + 1];
        }
        float* so = sin + img * 5070 + orow * 390;
        #pragma unroll
        for (int pp = 0; pp < 4; pp++) {
            int p = p0 + pp;
            if (p < 13) {
                float* sp = so + p * 30 + co0;
                #pragma unroll
                for (int c = 0; c < 5; c++) {
                    float lo, hi;
                    upk2(acc[pp][c], lo, hi);
                    sp[2 * c]     = fmaxf(lo + bl[c], 0.f);
                    sp[2 * c + 1] = fmaxf(hi + bh[c], 0.f);
                }
            }
        }
    }
    __syncthreads();
    for (int i = tid; i < 3 * 5070; i += 512) {
        int img2 = i / 5070;
        if (img0 + img2 < NIMG)
            out[(size_t)(img0 + img2) * 5070 + (i - img2 * 5070)] =
                sin[img2 * 5070 + (i - img2 * 5070)];
    }
}

// ---------------- persistent LSTM: all 55 timesteps in one kernel -----------
#define SHP 82
__global__ __launch_bounds__(512, 1)
void lstm_persist(const float* __restrict__ xw, const float* __restrict__ Wh,
                  float* __restrict__ hs) {
    extern __shared__ float sm[];
    float* sW = sm;              // [100][400]
    float* sh = sm + 40000;      // 2 x [100][SHP]
    const int tid  = threadIdx.x;
    const int row0 = blockIdx.x * 74;

    for (int i = tid; i < 40000; i += 512) sW[i] = Wh[i];
    for (int i = tid; i < 2 * 100 * SHP; i += 512) sh[i] = 0.f;
    __syncthreads();

    const int ut = tid % 50;
    const int rt = tid / 50;
    const int u0 = 2 * ut;
    const bool on = tid < 500;

    int  rowg[8];
    bool val[8];
    #pragma unroll
    for (int j = 0; j < 8; j++) {
        int r = rt * 8 + j;
        rowg[j] = row0 + r;
        val[j] = on && (r < 74) && (rowg[j] < NN);
    }
    float cc[8][2];
    #pragma unroll
    for (int j = 0; j < 8; j++) { cc[j][0] = 0.f; cc[j][1] = 0.f; }

    int cur = 0;
    for (int t = 0; t < TSTEPS; t++) {
        const float* xwt = xw + (size_t)t * NN * 400;
        ull acc[8][4];
        #pragma unroll
        for (int j = 0; j < 8; j++) {
            if (val[j]) {
                const float* zr = xwt + (size_t)rowg[j] * 400 + u0;
                #pragma unroll
                for (int g = 0; g < 4; g++)
                    acc[j][g] = *reinterpret_cast<const ull*>(zr + g * 100);
            } else {
                #pragma unroll
                for (int g = 0; g < 4; g++) acc[j][g] = 0ull;
            }
        }

        if (t > 0) {
            const float* shc = sh + cur * (100 * SHP);
            const int rb = rt * 8;
            #pragma unroll 4
            for (int k = 0; k < 100; k++) {
                const float* wk = sW + k * 400 + u0;
                ull wq0 = *reinterpret_cast<const ull*>(wk);
                ull wq1 = *reinterpret_cast<const ull*>(wk + 100);
                ull wq2 = *reinterpret_cast<const ull*>(wk + 200);
                ull wq3 = *reinterpret_cast<const ull*>(wk + 300);
                const float* hv = shc + k * SHP + rb;
                ull hp[4];
                #pragma unroll
                for (int q = 0; q < 4; q++)
                    hp[q] = *reinterpret_cast<const ull*>(&hv[2 * q]);
                #pragma unroll
                for (int q = 0; q < 4; q++) {
                    float he, ho;
                    upk2(hp[q], he, ho);
                    ull ade = pk2(he, he);
                    fma2(acc[2 * q][0], ade, wq0);
                    fma2(acc[2 * q][1], ade, wq1);
                    fma2(acc[2 * q][2], ade, wq2);
                    fma2(acc[2 * q][3], ade, wq3);
                    ull ado = pk2(ho, ho);
                    fma2(acc[2 * q + 1][0], ado, wq0);
                    fma2(acc[2 * q + 1][1], ado, wq1);
                    fma2(acc[2 * q + 1][2], ado, wq2);
                    fma2(acc[2 * q + 1][3], ado, wq3);
                }
            }
        }

        float* shn = sh + (cur ^ 1) * (100 * SHP);
        float* hst = hs + (size_t)t * NN * HL;
        #pragma unroll
        for (int j = 0; j < 8; j++) {
            int r = rt * 8 + j;
            if (on && r < 74) {
                float i0, i1, j0, j1, f0, f1, o0, o1;
                upk2(acc[j][0], i0, i1);
                upk2(acc[j][1], j0, j1);
                upk2(acc[j][2], f0, f1);
                upk2(acc[j][3], o0, o1);
                float c0 = sigm(f0 + 1.f) * cc[j][0] + sigm(i0) * tanha(j0);
                float c1 = sigm(f1 + 1.f) * cc[j][1] + sigm(i1) * tanha(j1);
                cc[j][0] = c0; cc[j][1] = c1;
                float h0 = sigm(o0) * tanha(c0);
                float h1 = sigm(o1) * tanha(c1);
                shn[u0 * SHP + r]       = h0;
                shn[(u0 + 1) * SHP + r] = h1;
                if (rowg[j] < NN)
                    *reinterpret_cast<float2*>(&hst[(size_t)rowg[j] * HL + u0]) =
                        make_float2(h0, h1);
            }
        }
        cur ^= 1;
        __syncthreads();
    }
}

// ---------------- final 1x1 conv (100 -> 1) + output transpose --------------
__global__ void final_proj(const float* __restrict__ hs2, const float* __restrict__ we,
                           const float* __restrict__ be, float* __restrict__ out) {
    long r = (long)blockIdx.x * blockDim.x + threadIdx.x;
    if (r >= (long)NROWS) return;
    int n = (int)(r % NN);
    int l = (int)(r / NN);
    const float4* row = reinterpret_cast<const float4*>(hs2 + (size_t)r * HL);
    const float4* wv  = reinterpret_cast<const float4*>(we);
    float acc = 0.f;
    #pragma unroll
    for (int i = 0; i < 25; i++) {
        float4 v = row[i], w = wv[i];
        acc += v.x * w.x + v.y * w.y + v.z * w.z + v.w * w.w;
    }
    out[(size_t)n * 55 + l] = acc + be[0];
}

// ---------------- host side -------------------------------------------------
extern "C" void kernel_launch(void* const* d_in, const int* in_sizes, int n_in,
                              void* d_out, int out_size) {
    (void)in_sizes; (void)n_in; (void)out_size;
    const float* x = (const float*)d_in[0];
    const float* w1[4] = {(const float*)d_in[1], (const float*)d_in[3],
                          (const float*)d_in[5], (const float*)d_in[7]};
    const float* b1[4] = {(const float*)d_in[2], (const float*)d_in[4],
                          (const float*)d_in[6], (const float*)d_in[8]};
    const float* w2[4] = {(const float*)d_in[9],  (const float*)d_in[11],
                          (const float*)d_in[13], (const float*)d_in[15]};
    const float* b2[4] = {(const float*)d_in[10], (const float*)d_in[12],
                          (const float*)d_in[14], (const float*)d_in[16]};
    const float* lw1 = (const float*)d_in[17];
    const float* lb1 = (const float*)d_in[18];
    const float* lw2 = (const float*)d_in[19];
    const float* lb2 = (const float*)d_in[20];
    const float* we  = (const float*)d_in[21];
    const float* be  = (const float*)d_in[22];
    float* out = (float*)d_out;

    void *p0, *p1, *pxw, *ph1, *ph2;
    cudaGetSymbolAddress(&p0,  g_act0);
    cudaGetSymbolAddress(&p1,  g_act1);
    cudaGetSymbolAddress(&pxw, g_xw);
    cudaGetSymbolAddress(&ph1, g_hs1);
    cudaGetSymbolAddress(&ph2, g_hs2);
    float* act0 = (float*)p0;
    float* act1 = (float*)p1;
    float* xw   = (float*)pxw;
    float* hs1  = (float*)ph1;
    float* hs2  = (float*)ph2;

    const size_t conv_sm  = 50040u * sizeof(float);                     // 200160
    const size_t lstm_sm  = (40000u + 2u * 100u * SHP) * sizeof(float); // 225600
    const size_t c1_sm    = (256u * C1_STG + 3420u + 120u) * sizeof(float); // 47952
    const size_t g30_sm   = (size_t)(30 * 231) * sizeof(float);         // 27720
    const size_t g100_sm  = (size_t)(100 * 231) * sizeof(float);        // 92400

    cudaFuncSetAttribute(conv5x5_v8, cudaFuncAttributeMaxDynamicSharedMemorySize,
                         (int)conv_sm);
    cudaFuncSetAttribute(lstm_persist, cudaFuncAttributeMaxDynamicSharedMemorySize,
                         (int)lstm_sm);
    cudaFuncSetAttribute((const void*)gemm_xw<100>,
                         cudaFuncAttributeMaxDynamicSharedMemorySize, (int)g100_sm);

    // 1) input transpose
    {
        long total = (long)NROWS * 6;
        transpose_in<<<(unsigned)((total + 255) / 256), 256>>>(x, act0);
    }

    // 2) fused 1x1 conv chain (4 layers, one kernel)
    {
        const unsigned grid = (NROWS + 255) / 256;   // 2324
        conv1_fused<<<grid, 128, c1_sm>>>(act0,
                                          w1[0], b1[0], w1[1], b1[1],
                                          w1[2], b1[2], w1[3], b1[3],
                                          act1, NROWS);
    }

    // 3) four 5x5 SAME convs (P=4, 468 active threads)
    {
        const int grid = (NIMG + 2) / 3;   // 1174
        conv5x5_v8<<<grid, 512, conv_sm>>>(act1, w2[0], b2[0], act0);
        conv5x5_v8<<<grid, 512, conv_sm>>>(act0, w2[1], b2[1], act1);
        conv5x5_v8<<<grid, 512, conv_sm>>>(act1, w2[2], b2[2], act0);
        conv5x5_v8<<<grid, 512, conv_sm>>>(act0, w2[3], b2[3], act1);
    }

    const unsigned GY = (NROWS + 127) / 128;   // 4648

    // 4) LSTM layer 1
    gemm_xw<30><<<dim3(4, GY), 320, g30_sm>>>(act1, lw1, lb1, xw, NROWS);
    lstm_persist<<<147, 512, lstm_sm>>>(xw, lw1 + (size_t)30 * 400, hs1);

    //    LSTM layer 2
    gemm_xw<100><<<dim3(4, GY), 320, g100_sm>>>(hs1, lw2, lb2, xw, NROWS);
    lstm_persist<<<147, 512, lstm_sm>>>(xw, lw2 + (size_t)100 * 400, hs2);

    // 5) final projection + output transpose
    final_proj<<<(NROWS + 255) / 256, 256>>>(hs2, we, be, out);
}

// round 15
// speedup vs baseline: 1.1173x; 1.0262x over previous
#include <cuda_runtime.h>
#include <cuda_bf16.h>
#include <cstdint>

#define NROWS 594880   // 55 * 64 * 169
#define NN    10816    // 64 * 169 rows per timestep
#define TSTEPS 55
#define HL    100
#define NIMG  3520     // 55 * 64 images of 13x13

typedef unsigned long long ull;

// ---------------- f32x2 packed-math helpers (sm_103a FFMA2) -----------------
__device__ __forceinline__ ull pk2(float lo, float hi) {
    ull r; asm("mov.b64 %0,{%1,%2};" : "=l"(r) : "f"(lo), "f"(hi)); return r;
}
__device__ __forceinline__ void upk2(ull v, float& lo, float& hi) {
    asm("mov.b64 {%0,%1},%2;" : "=f"(lo), "=f"(hi) : "l"(v));
}
__device__ __forceinline__ void fma2(ull& d, ull a, ull b) {
    asm("fma.rn.f32x2 %0,%1,%2,%0;" : "+l"(d) : "l"(a), "l"(b));
}

__device__ __forceinline__ float sigm(float x) {
    return __fdividef(1.f, 1.f + __expf(-x));
}
__device__ __forceinline__ float tanha(float x) {
    return __fdividef(2.f, 1.f + __expf(-2.f * x)) - 1.f;
}

// ---------------- warp-level HMMA: m16n8k16 bf16 -> fp32 --------------------
__device__ __forceinline__ void mma16816(float* c, uint32_t a0, uint32_t a1,
                                         uint32_t a2, uint32_t a3,
                                         uint32_t b0, uint32_t b1) {
    asm volatile(
        "mma.sync.aligned.m16n8k16.row.col.f32.bf16.bf16.f32 "
        "{%0,%1,%2,%3}, {%4,%5,%6,%7}, {%8,%9}, {%0,%1,%2,%3};"
        : "+f"(c[0]), "+f"(c[1]), "+f"(c[2]), "+f"(c[3])
        : "r"(a0), "r"(a1), "r"(a2), "r"(a3), "r"(b0), "r"(b1));
}

// ---------------- static device scratch -------------------------------------
__device__ float g_act0[(size_t)NROWS * 30];
__device__ float g_act1[(size_t)NROWS * 30];
__device__ float g_xw [(size_t)NROWS * 400];
__device__ float g_hs1[(size_t)NROWS * HL];
__device__ float g_hs2[(size_t)NROWS * HL];

// ---------------- input transpose -------------------------------------------
__global__ void transpose_in(const float* __restrict__ x, float* __restrict__ y) {
    long idx = (long)blockIdx.x * blockDim.x + threadIdx.x;
    const long total = (long)NROWS * 6;
    if (idx >= total) return;
    int  c4  = (int)(idx % 6);
    long row = idx / 6;
    int  pix = (int)(row % 169);
    long t1  = row / 169;
    int  b   = (int)(t1 % 64);
    int  l   = (int)(t1 / 64);
    long src = (((long)(b * 169 + pix)) * 55 + l) * 24 + c4 * 4;
    reinterpret_cast<float4*>(y)[row * 6 + c4] =
        *reinterpret_cast<const float4*>(x + src);
}

// ---------------- fused 1x1 conv chain (unchanged, R12) ---------------------
#define C1_STG 33
__global__ __launch_bounds__(128, 3)
void conv1_fused(const float* __restrict__ A,
                 const float* __restrict__ w0, const float* __restrict__ b0,
                 const float* __restrict__ w1, const float* __restrict__ b1,
                 const float* __restrict__ w2, const float* __restrict__ b2,
                 const float* __restrict__ w3, const float* __restrict__ b3,
                 float* __restrict__ Cout, long M) {
    extern __shared__ float sm[];
    float* stage = sm;
    float* sw    = sm + 256 * C1_STG;
    float* sb    = sw + 3420;

    const int tid  = threadIdx.x;
    const long row0 = (long)blockIdx.x * 256;

    for (int i = tid; i < 720; i += 128) sw[i] = w0[i];
    for (int i = tid; i < 900; i += 128) {
        sw[720 + i]  = w1[i];
        sw[1620 + i] = w2[i];
        sw[2520 + i] = w3[i];
    }
    if (tid < 30) {
        sb[tid] = b0[tid]; sb[30 + tid] = b1[tid];
        sb[60 + tid] = b2[tid]; sb[90 + tid] = b3[tid];
    }
    for (int f = tid; f < 1536; f += 128) {
        int r = f / 6, c4 = f - r * 6;
        long gr = row0 + r;
        float4 v = make_float4(0.f, 0.f, 0.f, 0.f);
        if (gr < M) v = *reinterpret_cast<const float4*>(A + gr * 24 + 4 * c4);
        float* d = &stage[r * C1_STG + 4 * c4];
        d[0] = v.x; d[1] = v.y; d[2] = v.z; d[3] = v.w;
    }
    __syncthreads();

    float a0[30], a1[30];
    {
        const float* s0 = &stage[(2 * tid) * C1_STG];
        const float* s1 = &stage[(2 * tid + 1) * C1_STG];
        #pragma unroll
        for (int k = 0; k < 24; k++) { a0[k] = s0[k]; a1[k] = s1[k]; }
    }

    ull acc0[15], acc1[15];
    #pragma unroll 1
    for (int layer = 0; layer < 4; layer++) {
        const int K = (layer == 0) ? 24 : 30;
        const float* wl = sw + ((layer == 0) ? 0 : 720 + (layer - 1) * 900);
        const float* bl = sb + layer * 30;
        #pragma unroll
        for (int p = 0; p < 15; p++) { acc0[p] = 0ull; acc1[p] = 0ull; }
        #pragma unroll 6
        for (int k = 0; k < K; k++) {
            ull ad0 = pk2(a0[k], a0[k]);
            ull ad1 = pk2(a1[k], a1[k]);
            const ull* wk = reinterpret_cast<const ull*>(&wl[k * 30]);
            #pragma unroll
            for (int p = 0; p < 15; p++) {
                ull bv = wk[p];
                fma2(acc0[p], ad0, bv);
                fma2(acc1[p], ad1, bv);
            }
        }
        #pragma unroll
        for (int p = 0; p < 15; p++) {
            float l0, h0, l1, h1;
            upk2(acc0[p], l0, h0);
            upk2(acc1[p], l1, h1);
            float be = bl[2 * p], bo = bl[2 * p + 1];
            a0[2 * p]     = fmaxf(l0 + be, 0.f);
            a0[2 * p + 1] = fmaxf(h0 + bo, 0.f);
            a1[2 * p]     = fmaxf(l1 + be, 0.f);
            a1[2 * p + 1] = fmaxf(h1 + bo, 0.f);
        }
    }

    __syncthreads();
    {
        float* s0 = &stage[(2 * tid) * C1_STG];
        float* s1 = &stage[(2 * tid + 1) * C1_STG];
        #pragma unroll
        for (int k = 0; k < 30; k++) { s0[k] = a0[k]; s1[k] = a1[k]; }
    }
    __syncthreads();
    for (int f = tid; f < 256 * 15; f += 128) {
        int r = f / 15, c2 = f - r * 15;
        long gr = row0 + r;
        if (gr < M) {
            const float* s = &stage[r * C1_STG + 2 * c2];
            *reinterpret_cast<float2*>(&Cout[gr * 30 + 2 * c2]) =
                make_float2(s[0], s[1]);
        }
    }
}

// ---------------- HMMA bf16-split GEMM: C[M,400] = A[M,K]@W[K,400] + bias ---
// Block: 128 rows x 100 cols (grid 4 x ceil(M/128)), 256 threads / 8 warps.
// A,W split to bf16 hi/lo in smem (in-kernel); warp computes 16 rows x 13
// m16n8 tiles; C = Ah@Wh + Ah@Wl + Al@Wh (fp32 accum). Fragments loaded
// directly via the documented m16n8k16 lane layout. Strides padded so
// quarter-row LDS hit distinct banks.
template<int K, int K16, int ASTR>
__global__ __launch_bounds__(256)
void gemm_mma(const float* __restrict__ A, const float* __restrict__ W,
              const float* __restrict__ bias, float* __restrict__ C, long M) {
    constexpr int KBF = K16 * 16;
    extern __shared__ char smc[];
    __nv_bfloat16* sAh = reinterpret_cast<__nv_bfloat16*>(smc);
    __nv_bfloat16* sAl = sAh + 128 * ASTR;
    __nv_bfloat16* sBh = sAh + 2 * 128 * ASTR;
    __nv_bfloat16* sBl = sBh + 104 * ASTR;
    float* stage = reinterpret_cast<float*>(smc);   // alias post-MMA, stride 106

    const int tid = threadIdx.x;
    const int wid = tid >> 5, lid = tid & 31;
    const long row0 = (long)blockIdx.y * 128;
    const int  col0 = blockIdx.x * 100;

    // A -> bf16 hi/lo split (coalesced over k)
    for (int idx = tid; idx < 128 * KBF; idx += 256) {
        int r = idx / KBF, k = idx - r * KBF;
        long gr = row0 + r;
        float x = (k < K && gr < M) ? A[gr * (long)K + k] : 0.f;
        __nv_bfloat16 h = __float2bfloat16(x);
        __nv_bfloat16 l = __float2bfloat16(x - __bfloat162float(h));
        sAh[r * ASTR + k] = h;
        sAl[r * ASTR + k] = l;
    }
    // W slice -> transposed [n][k] bf16 hi/lo (W is L2-resident, 160KB)
    for (int idx = tid; idx < 104 * KBF; idx += 256) {
        int n = idx / KBF, k = idx - n * KBF;
        float x = (k < K && n < 100) ? W[(size_t)k * 400 + col0 + n] : 0.f;
        __nv_bfloat16 h = __float2bfloat16(x);
        __nv_bfloat16 l = __float2bfloat16(x - __bfloat162float(h));
        sBh[n * ASTR + k] = h;
        sBl[n * ASTR + k] = l;
    }
    __syncthreads();

    float acc[13][4];
    #pragma unroll
    for (int nt = 0; nt < 13; nt++)
        #pragma unroll
        for (int i = 0; i < 4; i++) acc[nt][i] = 0.f;

    const int rq = wid * 16 + (lid >> 2);   // rows rq, rq+8
    const int kq = (lid & 3) * 2;           // k pair base
    const int nq = lid >> 2;                // n within tile

    #pragma unroll 1
    for (int ks = 0; ks < K16; ks++) {
        const int kb = ks * 16 + kq;
        uint32_t ah0 = *reinterpret_cast<const uint32_t*>(&sAh[rq * ASTR + kb]);
        uint32_t ah1 = *reinterpret_cast<const uint32_t*>(&sAh[(rq + 8) * ASTR + kb]);
        uint32_t ah2 = *reinterpret_cast<const uint32_t*>(&sAh[rq * ASTR + kb + 8]);
        uint32_t ah3 = *reinterpret_cast<const uint32_t*>(&sAh[(rq + 8) * ASTR + kb + 8]);
        uint32_t al0 = *reinterpret_cast<const uint32_t*>(&sAl[rq * ASTR + kb]);
        uint32_t al1 = *reinterpret_cast<const uint32_t*>(&sAl[(rq + 8) * ASTR + kb]);
        uint32_t al2 = *reinterpret_cast<const uint32_t*>(&sAl[rq * ASTR + kb + 8]);
        uint32_t al3 = *reinterpret_cast<const uint32_t*>(&sAl[(rq + 8) * ASTR + kb + 8]);
        #pragma unroll
        for (int nt = 0; nt < 13; nt++) {
            const int nb = (nt * 8 + nq) * ASTR + kb;
            uint32_t bh0 = *reinterpret_cast<const uint32_t*>(&sBh[nb]);
            uint32_t bh1 = *reinterpret_cast<const uint32_t*>(&sBh[nb + 8]);
            uint32_t bl0 = *reinterpret_cast<const uint32_t*>(&sBl[nb]);
            uint32_t bl1 = *reinterpret_cast<const uint32_t*>(&sBl[nb + 8]);
            mma16816(acc[nt], ah0, ah1, ah2, ah3, bh0, bh1);
            mma16816(acc[nt], ah0, ah1, ah2, ah3, bl0, bl1);
            mma16816(acc[nt], al0, al1, al2, al3, bh0, bh1);
        }
    }
    __syncthreads();   // all smem reads done -> stage alias safe

    // stage C fragments (row/col per m16n8 C layout), then coalesced store
    #pragma unroll
    for (int nt = 0; nt < 13; nt++) {
        int c = nt * 8 + kq;
        *reinterpret_cast<float2*>(&stage[rq * 106 + c]) =
            make_float2(acc[nt][0], acc[nt][1]);
        *reinterpret_cast<float2*>(&stage[(rq + 8) * 106 + c]) =
            make_float2(acc[nt][2], acc[nt][3]);
    }
    __syncthreads();
    for (int i = tid; i < 128 * 100; i += 256) {
        int r = i / 100, c = i - r * 100;
        long gr = row0 + r;
        if (gr < M)
            C[gr * 400 + col0 + c] = stage[r * 106 + c] + bias[col0 + c];
    }
}

// ---------------- 5x5 SAME conv v8 (unchanged, R12) -------------------------
#define CONV_SIN 9180
__device__ __forceinline__ void conv_tile8(const float* __restrict__ vbase,
                                           const float* __restrict__ sw,
                                           int orow, int co0, ull (&acc)[4][5]) {
    #pragma unroll 2
    for (int ci = 0; ci < 30; ci++) {
        const float* bci = vbase + ci * 306;
        #pragma unroll 1
        for (int ki = 0; ki < 5; ki++) {
            const float* vrow = bci + (orow + ki) * 18;
            ull dup[8];
            #pragma unroll
            for (int q = 0; q < 8; q++) {
                float t = vrow[q];
                dup[q] = pk2(t, t);
            }
            #pragma unroll
            for (int kj = 0; kj < 5; kj++) {
                const ull* wq = reinterpret_cast<const ull*>(
                    sw + ((ki * 5 + kj) * 30 + ci) * 30 + co0);
                ull w0 = wq[0], w1 = wq[1], w2 = wq[2], w3 = wq[3], w4 = wq[4];
                #pragma unroll
                for (int pp = 0; pp < 4; pp++) {
                    ull a = dup[pp + kj];
                    fma2(acc[pp][0], a, w0);
                    fma2(acc[pp][1], a, w1);
                    fma2(acc[pp][2], a, w2);
                    fma2(acc[pp][3], a, w3);
                    fma2(acc[pp][4], a, w4);
                }
            }
        }
    }
}

__global__ __launch_bounds__(512, 1)
void conv5x5_v8(const float* __restrict__ in, const float* __restrict__ w,
                const float* __restrict__ bias, float* __restrict__ out) {
    extern __shared__ float sm[];
    float* sin = sm;
    float* sw  = sm + 27540;

    const int tid  = threadIdx.x;
    const int img0 = blockIdx.x * 3;

    for (int i = tid; i < 3 * CONV_SIN; i += 512) sin[i] = 0.f;
    for (int i = tid; i < 22500; i += 512) sw[i] = w[i];
    __syncthreads();
    for (int i = tid; i < 3 * 5070; i += 512) {
        int img = i / 5070, rem = i - img * 5070;
        if (img0 + img < NIMG) {
            int p = rem / 30, ci = rem - p * 30;
            sin[img * CONV_SIN + ci * 306 + (p / 13 + 2) * 18 + (p % 13 + 2)] =
                in[(size_t)(img0 + img) * 5070 + rem];
        }
    }
    __syncthreads();

    const int  cog  = tid / 156;
    const int  rem  = tid - cog * 156;
    const int  img  = rem / 52;
    const int  rem2 = rem - img * 52;
    const int  orow = rem2 / 4;
    const int  pg   = rem2 & 3;
    const int  co0  = cog * 10;
    const int  p0   = pg * 4;
    const bool on   = (tid < 468);

    ull acc[4][5];
    #pragma unroll
    for (int p = 0; p < 4; p++)
        #pragma unroll
        for (int c = 0; c < 5; c++) acc[p][c] = 0ull;

    if (on)
        conv_tile8(sin + img * CONV_SIN + p0, sw, orow, co0, acc);

    __syncthreads();
    if (on) {
        float bl[5], bh[5];
        #pragma unroll
        for (int c = 0; c < 5; c++) {
            bl[c] = bias[co0 + 2 * c];
            bh[c] = bias[co0 + 2 * c + 1];
        }
        float* so = sin + img * 5070 + orow * 390;
        #pragma unroll
        for (int pp = 0; pp < 4; pp++) {
            int p = p0 + pp;
            if (p < 13) {
                float* sp = so + p * 30 + co0;
                #pragma unroll
                for (int c = 0; c < 5; c++) {
                    float lo, hi;
                    upk2(acc[pp][c], lo, hi);
                    sp[2 * c]     = fmaxf(lo + bl[c], 0.f);
                    sp[2 * c + 1] = fmaxf(hi + bh[c], 0.f);
                }
            }
        }
    }
    __syncthreads();
    for (int i = tid; i < 3 * 5070; i += 512) {
        int img2 = i / 5070;
        if (img0 + img2 < NIMG)
            out[(size_t)(img0 + img2) * 5070 + (i - img2 * 5070)] =
                sin[img2 * 5070 + (i - img2 * 5070)];
    }
}

// ---------------- persistent LSTM (unchanged, R12) --------------------------
#define SHP 82
__global__ __launch_bounds__(512, 1)
void lstm_persist(const float* __restrict__ xw, const float* __restrict__ Wh,
                  float* __restrict__ hs) {
    extern __shared__ float sm[];
    float* sW = sm;
    float* sh = sm + 40000;
    const int tid  = threadIdx.x;
    const int row0 = blockIdx.x * 74;

    for (int i = tid; i < 40000; i += 512) sW[i] = Wh[i];
    for (int i = tid; i < 2 * 100 * SHP; i += 512) sh[i] = 0.f;
    __syncthreads();

    const int ut = tid % 50;
    const int rt = tid / 50;
    const int u0 = 2 * ut;
    const bool on = tid < 500;

    int  rowg[8];
    bool val[8];
    #pragma unroll
    for (int j = 0; j < 8; j++) {
        int r = rt * 8 + j;
        rowg[j] = row0 + r;
        val[j] = on && (r < 74) && (rowg[j] < NN);
    }
    float cc[8][2];
    #pragma unroll
    for (int j = 0; j < 8; j++) { cc[j][0] = 0.f; cc[j][1] = 0.f; }

    int cur = 0;
    for (int t = 0; t < TSTEPS; t++) {
        const float* xwt = xw + (size_t)t * NN * 400;
        ull acc[8][4];
        #pragma unroll
        for (int j = 0; j < 8; j++) {
            if (val[j]) {
                const float* zr = xwt + (size_t)rowg[j] * 400 + u0;
                #pragma unroll
                for (int g = 0; g < 4; g++)
                    acc[j][g] = *reinterpret_cast<const ull*>(zr + g * 100);
            } else {
                #pragma unroll
                for (int g = 0; g < 4; g++) acc[j][g] = 0ull;
            }
        }

        if (t > 0) {
            const float* shc = sh + cur * (100 * SHP);
            const int rb = rt * 8;
            #pragma unroll 4
            for (int k = 0; k < 100; k++) {
                const float* wk = sW + k * 400 + u0;
                ull wq0 = *reinterpret_cast<const ull*>(wk);
                ull wq1 = *reinterpret_cast<const ull*>(wk + 100);
                ull wq2 = *reinterpret_cast<const ull*>(wk + 200);
                ull wq3 = *reinterpret_cast<const ull*>(wk + 300);
                const float* hv = shc + k * SHP + rb;
                ull hp[4];
                #pragma unroll
                for (int q = 0; q < 4; q++)
                    hp[q] = *reinterpret_cast<const ull*>(&hv[2 * q]);
                #pragma unroll
                for (int q = 0; q < 4; q++) {
                    float he, ho;
                    upk2(hp[q], he, ho);
                    ull ade = pk2(he, he);
                    fma2(acc[2 * q][0], ade, wq0);
                    fma2(acc[2 * q][1], ade, wq1);
                    fma2(acc[2 * q][2], ade, wq2);
                    fma2(acc[2 * q][3], ade, wq3);
                    ull ado = pk2(ho, ho);
                    fma2(acc[2 * q + 1][0], ado, wq0);
                    fma2(acc[2 * q + 1][1], ado, wq1);
                    fma2(acc[2 * q + 1][2], ado, wq2);
                    fma2(acc[2 * q + 1][3], ado, wq3);
                }
            }
        }

        float* shn = sh + (cur ^ 1) * (100 * SHP);
        float* hst = hs + (size_t)t * NN * HL;
        #pragma unroll
        for (int j = 0; j < 8; j++) {
            int r = rt * 8 + j;
            if (on && r < 74) {
                float i0, i1, j0, j1, f0, f1, o0, o1;
                upk2(acc[j][0], i0, i1);
                upk2(acc[j][1], j0, j1);
                upk2(acc[j][2], f0, f1);
                upk2(acc[j][3], o0, o1);
                float c0 = sigm(f0 + 1.f) * cc[j][0] + sigm(i0) * tanha(j0);
                float c1 = sigm(f1 + 1.f) * cc[j][1] + sigm(i1) * tanha(j1);
                cc[j][0] = c0; cc[j][1] = c1;
                float h0 = sigm(o0) * tanha(c0);
                float h1 = sigm(o1) * tanha(c1);
                shn[u0 * SHP + r]       = h0;
                shn[(u0 + 1) * SHP + r] = h1;
                if (rowg[j] < NN)
                    *reinterpret_cast<float2*>(&hst[(size_t)rowg[j] * HL + u0]) =
                        make_float2(h0, h1);
            }
        }
        cur ^= 1;
        __syncthreads();
    }
}

// ---------------- final 1x1 conv (100 -> 1) + output transpose --------------
__global__ void final_proj(const float* __restrict__ hs2, const float* __restrict__ we,
                           const float* __restrict__ be, float* __restrict__ out) {
    long r = (long)blockIdx.x * blockDim.x + threadIdx.x;
    if (r >= (long)NROWS) return;
    int n = (int)(r % NN);
    int l = (int)(r / NN);
    const float4* row = reinterpret_cast<const float4*>(hs2 + (size_t)r * HL);
    const float4* wv  = reinterpret_cast<const float4*>(we);
    float acc = 0.f;
    #pragma unroll
    for (int i = 0; i < 25; i++) {
        float4 v = row[i], w = wv[i];
        acc += v.x * w.x + v.y * w.y + v.z * w.z + v.w * w.w;
    }
    out[(size_t)n * 55 + l] = acc + be[0];
}

// ---------------- host side -------------------------------------------------
extern "C" void kernel_launch(void* const* d_in, const int* in_sizes, int n_in,
                              void* d_out, int out_size) {
    (void)in_sizes; (void)n_in; (void)out_size;
    const float* x = (const float*)d_in[0];
    const float* w1[4] = {(const float*)d_in[1], (const float*)d_in[3],
                          (const float*)d_in[5], (const float*)d_in[7]};
    const float* b1[4] = {(const float*)d_in[2], (const float*)d_in[4],
                          (const float*)d_in[6], (const float*)d_in[8]};
    const float* w2[4] = {(const float*)d_in[9],  (const float*)d_in[11],
                          (const float*)d_in[13], (const float*)d_in[15]};
    const float* b2[4] = {(const float*)d_in[10], (const float*)d_in[12],
                          (const float*)d_in[14], (const float*)d_in[16]};
    const float* lw1 = (const float*)d_in[17];
    const float* lb1 = (const float*)d_in[18];
    const float* lw2 = (const float*)d_in[19];
    const float* lb2 = (const float*)d_in[20];
    const float* we  = (const float*)d_in[21];
    const float* be  = (const float*)d_in[22];
    float* out = (float*)d_out;

    void *p0, *p1, *pxw, *ph1, *ph2;
    cudaGetSymbolAddress(&p0,  g_act0);
    cudaGetSymbolAddress(&p1,  g_act1);
    cudaGetSymbolAddress(&pxw, g_xw);
    cudaGetSymbolAddress(&ph1, g_hs1);
    cudaGetSymbolAddress(&ph2, g_hs2);
    float* act0 = (float*)p0;
    float* act1 = (float*)p1;
    float* xw   = (float*)pxw;
    float* hs1  = (float*)ph1;
    float* hs2  = (float*)ph2;

    const size_t conv_sm  = 50040u * sizeof(float);
    const size_t lstm_sm  = (40000u + 2u * 100u * SHP) * sizeof(float);
    const size_t c1_sm    = (256u * C1_STG + 3420u + 120u) * sizeof(float);
    // gemm_mma smem: max(bf16 layout, fp32 stage 128*106*4=54272)
    const size_t gm1_sm = 54272u;                       // K=30 : layout 33408
    const size_t gm2_sm = 111360u;                      // K=100: layout 111360

    cudaFuncSetAttribute(conv5x5_v8, cudaFuncAttributeMaxDynamicSharedMemorySize,
                         (int)conv_sm);
    cudaFuncSetAttribute(lstm_persist, cudaFuncAttributeMaxDynamicSharedMemorySize,
                         (int)lstm_sm);
    cudaFuncSetAttribute((const void*)gemm_mma<30, 2, 36>,
                         cudaFuncAttributeMaxDynamicSharedMemorySize, (int)gm1_sm);
    cudaFuncSetAttribute((const void*)gemm_mma<100, 7, 120>,
                         cudaFuncAttributeMaxDynamicSharedMemorySize, (int)gm2_sm);

    // 1) input transpose
    {
        long total = (long)NROWS * 6;
        transpose_in<<<(unsigned)((total + 255) / 256), 256>>>(x, act0);
    }

    // 2) fused 1x1 conv chain
    {
        const unsigned grid = (NROWS + 255) / 256;
        conv1_fused<<<grid, 128, c1_sm>>>(act0,
                                          w1[0], b1[0], w1[1], b1[1],
                                          w1[2], b1[2], w1[3], b1[3],
                                          act1, NROWS);
    }

    // 3) four 5x5 SAME convs
    {
        const int grid = (NIMG + 2) / 3;
        conv5x5_v8<<<grid, 512, conv_sm>>>(act1, w2[0], b2[0], act0);
        conv5x5_v8<<<grid, 512, conv_sm>>>(act0, w2[1], b2[1], act1);
        conv5x5_v8<<<grid, 512, conv_sm>>>(act1, w2[2], b2[2], act0);
        conv5x5_v8<<<grid, 512, conv_sm>>>(act0, w2[3], b2[3], act1);
    }

    const unsigned GY128 = (NROWS + 127) / 128;   // 4648

    // 4) LSTM layer 1: HMMA bf16-split x-projection, persistent recurrence
    gemm_mma<30, 2, 36><<<dim3(4, GY128), 256, gm1_sm>>>(act1, lw1, lb1, xw, NROWS);
    lstm_persist<<<147, 512, lstm_sm>>>(xw, lw1 + (size_t)30 * 400, hs1);

    //    LSTM layer 2
    gemm_mma<100, 7, 120><<<dim3(4, GY128), 256, gm2_sm>>>(hs1, lw2, lb2, xw, NROWS);
    lstm_persist<<<147, 512, lstm_sm>>>(xw, lw2 + (size_t)100 * 400, hs2);

    // 5) final projection + output transpose
    final_proj<<<(NROWS + 255) / 256, 256>>>(hs2, we, be, out);
}